// round 10
// baseline (speedup 1.0000x reference)
#include <cuda_runtime.h>
#include <cuda_fp16.h>
#include <cstdint>

#define BB 8
#define SQL 2048
#define SKL 2048
#define DDIM 1024

// ---------------- static device scratch (no allocation allowed) ----------------
__device__ __align__(256) __half g_qh [BB * SQL * DDIM];
__device__ __align__(256) __half g_ql [BB * SQL * DDIM];
__device__ __align__(256) __half g_kh [BB * SKL * DDIM];
__device__ __align__(256) __half g_kl [BB * SKL * DDIM];
__device__ __align__(256) __half g_vh [BB * SKL * DDIM];
__device__ __align__(256) __half g_vl [BB * SKL * DDIM];
__device__ __align__(256) __half g_Wqh[DDIM * DDIM];
__device__ __align__(256) __half g_Wql[DDIM * DDIM];
__device__ __align__(256) __half g_Wkh[DDIM * DDIM];
__device__ __align__(256) __half g_Wkl[DDIM * DDIM];
__device__ __align__(256) __half g_Wvh[DDIM * DDIM];
__device__ __align__(256) __half g_Wvl[DDIM * DDIM];
__device__ __align__(256) __half g_Qph[BB * SQL * DDIM];
__device__ __align__(256) __half g_Qpl[BB * SQL * DDIM];
__device__ __align__(256) __half g_Kph[BB * SKL * DDIM];
__device__ __align__(256) __half g_Kpl[BB * SKL * DDIM];
__device__ __align__(256) __half g_VpT[DDIM * BB * SKL];   // [dv][b*SK + sk]
__device__ __align__(256) float  g_S  [(size_t)BB * SQL * SKL];
__device__ __align__(256) __half g_P  [(size_t)BB * SQL * SKL];

__device__ __forceinline__ uint32_t smem_u32(const void* p) {
    return (uint32_t)__cvta_generic_to_shared(p);
}

// ---------------- merged fp32 -> (hi,lo) fp16 split convert (y picks tensor) ----
__global__ void cvt_split3(const float* __restrict__ x0, __half* h0, __half* l0,
                           const float* __restrict__ x1, __half* h1, __half* l1,
                           const float* __restrict__ x2, __half* h2, __half* l2) {
    const float* x = (blockIdx.y == 0) ? x0 : (blockIdx.y == 1) ? x1 : x2;
    __half* hi = (blockIdx.y == 0) ? h0 : (blockIdx.y == 1) ? h1 : h2;
    __half* lo = (blockIdx.y == 0) ? l0 : (blockIdx.y == 1) ? l1 : l2;
    int i = blockIdx.x * blockDim.x + threadIdx.x;
    float4 v = ((const float4*)x)[i];
    __half a0 = __float2half_rn(v.x), a1 = __float2half_rn(v.y);
    __half a2 = __float2half_rn(v.z), a3 = __float2half_rn(v.w);
    __half b0 = __float2half_rn(v.x - __half2float(a0));
    __half b1 = __float2half_rn(v.y - __half2float(a1));
    __half b2 = __float2half_rn(v.z - __half2float(a2));
    __half b3 = __float2half_rn(v.w - __half2float(a3));
    ((__half2*)hi)[2 * i + 0] = __halves2half2(a0, a1);
    ((__half2*)hi)[2 * i + 1] = __halves2half2(a2, a3);
    ((__half2*)lo)[2 * i + 0] = __halves2half2(b0, b1);
    ((__half2*)lo)[2 * i + 1] = __halves2half2(b2, b3);
}

// ---------------- merged weight transpose + split (z picks matrix) ----------------
__global__ void wtrans3(const float* __restrict__ W0, __half* T0h, __half* T0l,
                        const float* __restrict__ W1, __half* T1h, __half* T1l,
                        const float* __restrict__ W2, __half* T2h, __half* T2l) {
    const float* W = (blockIdx.z == 0) ? W0 : (blockIdx.z == 1) ? W1 : W2;
    __half* WTh = (blockIdx.z == 0) ? T0h : (blockIdx.z == 1) ? T1h : T2h;
    __half* WTl = (blockIdx.z == 0) ? T0l : (blockIdx.z == 1) ? T1l : T2l;
    __shared__ float tile[32][33];
    int kb = blockIdx.x * 32, nb = blockIdx.y * 32;
    int tx = threadIdx.x, ty = threadIdx.y;
#pragma unroll
    for (int r = 0; r < 4; r++)
        tile[ty + 8 * r][tx] = W[(size_t)(kb + ty + 8 * r) * DDIM + nb + tx];
    __syncthreads();
#pragma unroll
    for (int r = 0; r < 4; r++) {
        float x = tile[tx][ty + 8 * r];
        __half h = __float2half_rn(x);
        size_t o = (size_t)(nb + ty + 8 * r) * DDIM + kb + tx;
        WTh[o] = h;
        WTl[o] = __float2half_rn(x - __half2float(h));
    }
}

// XOR swizzle: 64-byte k-rows (32 halves), 4 chunks of 16B per row.
#define OPB 8192   // bytes per operand tile: 128 rows * 64 B

__device__ __forceinline__ uint32_t swz_off(int row, int chunk) {
    return (uint32_t)(row * 64 + ((chunk ^ ((row >> 1) & 3)) << 4));
}

template <int N> __device__ __forceinline__ void cpwait() {
    asm volatile("cp.async.wait_group %0;\n" ::"n"(N));
}

#define LDSM4(R0, R1, R2, R3, addr)                                                  \
    asm volatile("ldmatrix.sync.aligned.m8n8.x4.shared.b16 {%0,%1,%2,%3}, [%4];"     \
                 : "=r"(R0), "=r"(R1), "=r"(R2), "=r"(R3) : "r"(addr))

#define MMA16(AA, BB_)                                                                       \
    asm volatile("mma.sync.aligned.m16n8k16.row.col.f32.f16.f16.f32 "                        \
                 "{%0,%1,%2,%3}, {%4,%5,%6,%7}, {%8,%9}, {%0,%1,%2,%3};"                     \
                 : "+f"(c[i][j][0]), "+f"(c[i][j][1]), "+f"(c[i][j][2]), "+f"(c[i][j][3])    \
                 : "r"(AA[i][0]), "r"(AA[i][1]), "r"(AA[i][2]), "r"(AA[i][3]),               \
                   "r"(BB_[j][0]), "r"(BB_[j][1]))

// =====================================================================
// Split-precision core: 3 mma passes (Ah*Bh + Ah*Bl + Al*Bh), fp32 accum,
// 3-stage cp.async pipeline, 1 barrier/k32-iter, short fragment live ranges.
// rtmode: 0 = bias + hi/lo split fp16 store; 1 = tanh+bias transposed fp16;
//         2 = fp32 store.
// =====================================================================
__device__ __forceinline__ void split_core(
    const __half* __restrict__ Ah, const __half* __restrict__ Al,
    const __half* __restrict__ Bh, const __half* __restrict__ Bl,
    void* __restrict__ C0b, void* __restrict__ C1b,
    const float* __restrict__ bias,
    int K, int lda, int ldb, int ldc, int gm, int gn, int rtmode, char* smem) {
    constexpr int STGB = 4 * OPB;   // 32 KB per stage
    const int tid = threadIdx.x, lane = tid & 31, warp = tid >> 5;
    const int wm = warp & 1, wn = warp >> 1;
    const int nk = K >> 5;

    float c[4][4][4];
#pragma unroll
    for (int i = 0; i < 4; i++)
#pragma unroll
        for (int j = 0; j < 4; j++)
#pragma unroll
            for (int r = 0; r < 4; r++) c[i][j][r] = 0.f;

    auto load_stage = [&](int s, int kt) {
        if (kt < nk) {
            char* stg = smem + s * STGB;
            const int k0 = kt * 32;
#pragma unroll
            for (int op = 0; op < 4; op++) {
                const __half* base = (op == 0) ? Ah : (op == 1) ? Al : (op == 2) ? Bh : Bl;
                const int r0 = (op < 2) ? gm : gn;
                const int ld = (op < 2) ? lda : ldb;
                char* dst0 = stg + op * OPB;
#pragma unroll
                for (int it = 0; it < 2; it++) {
                    int qq = tid + it * 256;
                    int r = qq >> 2, cc = qq & 3;
                    uint32_t dst = smem_u32(dst0 + swz_off(r, cc));
                    const __half* src = base + (size_t)(r0 + r) * ld + k0 + cc * 8;
                    asm volatile("cp.async.cg.shared.global [%0], [%1], 16;\n"
                                 ::"r"(dst), "l"(src));
                }
            }
        }
        asm volatile("cp.async.commit_group;\n");
    };

    load_stage(0, 0);
    load_stage(1, 1);

    uint32_t ah[4][4], al[4][4], bh[4][2], bl[4][2];

    auto ldA = [&](uint32_t (*d)[4], const char* base, int ks) {
#pragma unroll
        for (int i = 0; i < 4; i++) {
            int row = wm * 64 + i * 16 + (lane & 15);
            uint32_t o = swz_off(row, ks * 2 + (lane >> 4));
            LDSM4(d[i][0], d[i][1], d[i][2], d[i][3], smem_u32(base + o));
        }
    };
    auto ldB = [&](uint32_t (*d)[2], const char* base, int ks) {
#pragma unroll
        for (int j = 0; j < 4; j += 2) {
            int row = wn * 32 + (j + (lane >> 4)) * 8 + (lane & 7);
            uint32_t o = swz_off(row, ks * 2 + ((lane >> 3) & 1));
            LDSM4(d[j][0], d[j][1], d[j + 1][0], d[j + 1][1], smem_u32(base + o));
        }
    };
    auto mmaAB = [&](uint32_t (*A)[4], uint32_t (*B)[2]) {
#pragma unroll
        for (int i = 0; i < 4; i++)
#pragma unroll
            for (int j = 0; j < 4; j++) MMA16(A, B);
    };

    for (int kt = 0; kt < nk; kt++) {
        cpwait<1>();
        __syncthreads();
        const char* stg = smem + (kt % 3) * STGB;
        const char* sa = stg;
        const char* sb = stg + 2 * OPB;
        // ks = 0: short live ranges (hh -> hl -> lh)
        ldA(ah, sa, 0); ldB(bh, sb, 0);
        load_stage((kt + 2) % 3, kt + 2);
        mmaAB(ah, bh);
        ldB(bl, sb + OPB, 0); mmaAB(ah, bl);
        ldA(al, sa + OPB, 0); mmaAB(al, bh);
        // ks = 1
        ldA(ah, sa, 1); ldB(bh, sb, 1);
        mmaAB(ah, bh);
        ldB(bl, sb + OPB, 1); mmaAB(ah, bl);
        ldA(al, sa + OPB, 1); mmaAB(al, bh);
    }

    __syncthreads();

    if (rtmode == 2) {
        float* C = (float*)C0b;
#pragma unroll
        for (int i = 0; i < 4; i++)
#pragma unroll
            for (int j = 0; j < 4; j++) {
                int row = gm + wm * 64 + i * 16 + (lane >> 2);
                int col = gn + wn * 32 + j * 8 + ((lane & 3) << 1);
                float2 v0; v0.x = c[i][j][0]; v0.y = c[i][j][1];
                float2 v1; v1.x = c[i][j][2]; v1.y = c[i][j][3];
                *(float2*)(C + (size_t)row * ldc + col) = v0;
                *(float2*)(C + (size_t)(row + 8) * ldc + col) = v1;
            }
    } else if (rtmode == 0) {
        __half* Chi = (__half*)C0b;
        __half* Clo = (__half*)C1b;
#pragma unroll
        for (int i = 0; i < 4; i++)
#pragma unroll
            for (int j = 0; j < 4; j++) {
                int row = gm + wm * 64 + i * 16 + (lane >> 2);
                int col = gn + wn * 32 + j * 8 + ((lane & 3) << 1);
                float b0 = bias[col], b1 = bias[col + 1];
#pragma unroll
                for (int h = 0; h < 2; h++) {
                    float v0 = c[i][j][2 * h + 0] + b0;
                    float v1 = c[i][j][2 * h + 1] + b1;
                    __half h0 = __float2half_rn(v0), h1 = __float2half_rn(v1);
                    __half l0 = __float2half_rn(v0 - __half2float(h0));
                    __half l1 = __float2half_rn(v1 - __half2float(h1));
                    size_t o = (size_t)(row + 8 * h) * ldc + col;
                    *(__half2*)(Chi + o) = __halves2half2(h0, h1);
                    *(__half2*)(Clo + o) = __halves2half2(l0, l1);
                }
            }
    } else {  // rtmode == 1: tanh + transposed fp16 store via smem staging
        __half* st = (__half*)smem;  // 128*136 halves = 34816 B
#pragma unroll
        for (int i = 0; i < 4; i++)
#pragma unroll
            for (int j = 0; j < 4; j++) {
                int row = wm * 64 + i * 16 + (lane >> 2);
                int col = wn * 32 + j * 8 + ((lane & 3) << 1);
                float b0 = bias[gn + col], b1 = bias[gn + col + 1];
                st[(col + 0) * 136 + row + 0] = __float2half_rn(tanhf(c[i][j][0] + b0));
                st[(col + 1) * 136 + row + 0] = __float2half_rn(tanhf(c[i][j][1] + b1));
                st[(col + 0) * 136 + row + 8] = __float2half_rn(tanhf(c[i][j][2] + b0));
                st[(col + 1) * 136 + row + 8] = __float2half_rn(tanhf(c[i][j][3] + b1));
            }
        __syncthreads();
        __half* C = (__half*)C0b;
        for (int qq = tid; qq < 128 * 128 / 8; qq += 256) {
            int n = qq >> 4, m = (qq & 15) << 3;
            *(uint4*)(C + (size_t)(gn + n) * ldc + gm + m) = *(const uint4*)(st + n * 136 + m);
        }
    }
}

// =====================================================================
// Single-pass fp16 core (PV): 6-stage pipeline, prefetch distance 4,
// barrier every 2 k32-iters, fp32 store. nk must be even.
// =====================================================================
__device__ __forceinline__ void pv_core(
    const __half* __restrict__ A, const __half* __restrict__ B, float* __restrict__ C,
    int K, int lda, int ldb, int ldc, int gm, int gn, char* smem) {
    constexpr int STGB = 2 * OPB;   // 16 KB per stage
    const int tid = threadIdx.x, lane = tid & 31, warp = tid >> 5;
    const int wm = warp & 1, wn = warp >> 1;
    const int nk = K >> 5;

    float c[4][4][4];
#pragma unroll
    for (int i = 0; i < 4; i++)
#pragma unroll
        for (int j = 0; j < 4; j++)
#pragma unroll
            for (int r = 0; r < 4; r++) c[i][j][r] = 0.f;

    auto load_stage = [&](int s, int kt) {
        if (kt < nk) {
            char* stg = smem + s * STGB;
            const int k0 = kt * 32;
#pragma unroll
            for (int op = 0; op < 2; op++) {
                const __half* base = (op == 0) ? A : B;
                const int r0 = (op == 0) ? gm : gn;
                const int ld = (op == 0) ? lda : ldb;
                char* dst0 = stg + op * OPB;
#pragma unroll
                for (int it = 0; it < 2; it++) {
                    int qq = tid + it * 256;
                    int r = qq >> 2, cc = qq & 3;
                    uint32_t dst = smem_u32(dst0 + swz_off(r, cc));
                    const __half* src = base + (size_t)(r0 + r) * ld + k0 + cc * 8;
                    asm volatile("cp.async.cg.shared.global [%0], [%1], 16;\n"
                                 ::"r"(dst), "l"(src));
                }
            }
        }
        asm volatile("cp.async.commit_group;\n");
    };

#pragma unroll
    for (int t = 0; t < 4; t++) load_stage(t, t);   // prefetch distance 4

    uint32_t ah[4][4], bh[4][2];
    auto ldA = [&](const char* base, int ks) {
#pragma unroll
        for (int i = 0; i < 4; i++) {
            int row = wm * 64 + i * 16 + (lane & 15);
            uint32_t o = swz_off(row, ks * 2 + (lane >> 4));
            LDSM4(ah[i][0], ah[i][1], ah[i][2], ah[i][3], smem_u32(base + o));
        }
    };
    auto ldB = [&](const char* base, int ks) {
#pragma unroll
        for (int j = 0; j < 4; j += 2) {
            int row = wn * 32 + (j + (lane >> 4)) * 8 + (lane & 7);
            uint32_t o = swz_off(row, ks * 2 + ((lane >> 3) & 1));
            LDSM4(bh[j][0], bh[j][1], bh[j + 1][0], bh[j + 1][1], smem_u32(base + o));
        }
    };
    auto mmaAB = [&]() {
#pragma unroll
        for (int i = 0; i < 4; i++)
#pragma unroll
            for (int j = 0; j < 4; j++) MMA16(ah, bh);
    };
    auto body = [&](int kt) {
        const char* stg = smem + (kt % 6) * STGB;
        ldA(stg, 0); ldB(stg + OPB, 0);
        load_stage((kt + 4) % 6, kt + 4);
        mmaAB();
        ldA(stg, 1); ldB(stg + OPB, 1);
        mmaAB();
    };

    for (int kt = 0; kt < nk; kt += 2) {
        cpwait<3>();
        __syncthreads();         // covers slot reuse for this iter and the next
        body(kt);
        cpwait<3>();
        body(kt + 1);
    }

    __syncthreads();
#pragma unroll
    for (int i = 0; i < 4; i++)
#pragma unroll
        for (int j = 0; j < 4; j++) {
            int row = gm + wm * 64 + i * 16 + (lane >> 2);
            int col = gn + wn * 32 + j * 8 + ((lane & 3) << 1);
            float2 v0; v0.x = c[i][j][0]; v0.y = c[i][j][1];
            float2 v1; v1.x = c[i][j][2]; v1.y = c[i][j][3];
            *(float2*)(C + (size_t)row * ldc + col) = v0;
            *(float2*)(C + (size_t)(row + 8) * ldc + col) = v1;
        }
}

// --------- projection kernel: z picks {Q, K} ---------
struct ProjSet {
    const __half *Ah, *Al, *Bh, *Bl;
    __half *C0, *C1;
    const float* bias;
};

__global__ void __launch_bounds__(256, 2)
gemm_proj(ProjSet p0, ProjSet p1) {
    extern __shared__ __align__(128) char smem[];
    const ProjSet& p = (blockIdx.z == 0) ? p0 : p1;
    split_core(p.Ah, p.Al, p.Bh, p.Bl, p.C0, p.C1, p.bias,
               DDIM, DDIM, DDIM, DDIM, blockIdx.y * 128, blockIdx.x * 128, 0, smem);
}

// --------- mega kernel: z<8 -> scores batch z; z>=8 -> V projection tiles ---------
__global__ void __launch_bounds__(256, 2)
gemm_sv(const __half* Qph, const __half* Qpl, const __half* Kph, const __half* Kpl,
        float* S,
        const __half* vh, const __half* vl, const __half* Wvh, const __half* Wvl,
        __half* VpT, const float* bv) {
    extern __shared__ __align__(128) char smem[];
    int z = blockIdx.z;
    if (z < 8) {
        split_core(Qph + (size_t)z * SQL * DDIM, Qpl + (size_t)z * SQL * DDIM,
                   Kph + (size_t)z * SKL * DDIM, Kpl + (size_t)z * SKL * DDIM,
                   (float*)S + (size_t)z * SQL * SKL, nullptr, nullptr,
                   DDIM, DDIM, DDIM, SKL, blockIdx.y * 128, blockIdx.x * 128, 2, smem);
    } else {
        int t = (z - 8) * 256 + blockIdx.y * 16 + blockIdx.x;   // 0..1023
        split_core(vh, vl, Wvh, Wvl, VpT, nullptr, bv,
                   DDIM, DDIM, DDIM, BB * SKL, (t >> 3) * 128, (t & 7) * 128, 1, smem);
    }
}

// --------- PV kernel ---------
__global__ void __launch_bounds__(256, 2)
gemm_pv(const __half* __restrict__ P, const __half* __restrict__ VpT,
        float* __restrict__ O) {
    extern __shared__ __align__(128) char smem[];
    int b = blockIdx.z;
    pv_core(P + (size_t)b * SQL * SKL, VpT + (size_t)b * SKL,
            O + (size_t)b * SQL * DDIM,
            SKL, SKL, BB * SKL, DDIM, blockIdx.y * 128, blockIdx.x * 128, smem);
}

// ---------------- softmax over rows of S (+ int32 bool-mask add) -> fp16 P ----------------
__global__ void softmax_k(const float* __restrict__ S, const int* __restrict__ mask,
                          __half* __restrict__ P) {
    int row = blockIdx.x;
    int b = row >> 11;
    int t = threadIdx.x;
    const float4* s4 = (const float4*)(S + (size_t)row * SKL);
    const int4*   m4 = (const int4*)(mask + (size_t)b * SKL);

    float4 v[2];
    float mx = -3.4e38f;
#pragma unroll
    for (int i = 0; i < 2; i++) {
        float4 sv = s4[t + i * 256];
        int4 mv = m4[t + i * 256];
        sv.x += mv.x ? 1.0f : 0.0f;
        sv.y += mv.y ? 1.0f : 0.0f;
        sv.z += mv.z ? 1.0f : 0.0f;
        sv.w += mv.w ? 1.0f : 0.0f;
        v[i] = sv;
        mx = fmaxf(mx, fmaxf(fmaxf(sv.x, sv.y), fmaxf(sv.z, sv.w)));
    }
    __shared__ float red[8];
#pragma unroll
    for (int o = 16; o > 0; o >>= 1) mx = fmaxf(mx, __shfl_xor_sync(0xffffffffu, mx, o));
    if ((t & 31) == 0) red[t >> 5] = mx;
    __syncthreads();
    mx = red[0];
#pragma unroll
    for (int i = 1; i < 8; i++) mx = fmaxf(mx, red[i]);
    __syncthreads();

    float sum = 0.f;
#pragma unroll
    for (int i = 0; i < 2; i++) {
        v[i].x = __expf(v[i].x - mx);
        v[i].y = __expf(v[i].y - mx);
        v[i].z = __expf(v[i].z - mx);
        v[i].w = __expf(v[i].w - mx);
        sum += v[i].x + v[i].y + v[i].z + v[i].w;
    }
#pragma unroll
    for (int o = 16; o > 0; o >>= 1) sum += __shfl_xor_sync(0xffffffffu, sum, o);
    if ((t & 31) == 0) red[t >> 5] = sum;
    __syncthreads();
    sum = red[0];
#pragma unroll
    for (int i = 1; i < 8; i++) sum += red[i];

    float inv = 1.0f / sum;
    __half* Pr = P + (size_t)row * SKL;
#pragma unroll
    for (int i = 0; i < 2; i++) {
        __half2 h0 = __floats2half2_rn(v[i].x * inv, v[i].y * inv);
        __half2 h1 = __floats2half2_rn(v[i].z * inv, v[i].w * inv);
        uint2 pk;
        pk.x = *(uint32_t*)&h0;
        pk.y = *(uint32_t*)&h1;
        *(uint2*)(Pr + 4 * (t + i * 256)) = pk;
    }
}

// ---------------- launch ----------------
extern "C" void kernel_launch(void* const* d_in, const int* in_sizes, int n_in,
                              void* d_out, int out_size) {
    const float* q  = (const float*)d_in[0];
    const float* k  = (const float*)d_in[1];
    const float* v  = (const float*)d_in[2];
    const int*   mask = (const int*)d_in[3];
    const float* Wq = (const float*)d_in[4];
    const float* bq = (const float*)d_in[5];
    const float* Wk = (const float*)d_in[6];
    const float* bk = (const float*)d_in[7];
    const float* Wv = (const float*)d_in[8];
    const float* bv = (const float*)d_in[9];

    __half *qh, *ql, *kh, *kl, *vh, *vl;
    __half *Wqh, *Wql, *Wkh, *Wkl, *Wvh, *Wvl;
    __half *Qph, *Qpl, *Kph, *Kpl, *VpT, *P;
    float* S;
    cudaGetSymbolAddress((void**)&qh,  g_qh);  cudaGetSymbolAddress((void**)&ql,  g_ql);
    cudaGetSymbolAddress((void**)&kh,  g_kh);  cudaGetSymbolAddress((void**)&kl,  g_kl);
    cudaGetSymbolAddress((void**)&vh,  g_vh);  cudaGetSymbolAddress((void**)&vl,  g_vl);
    cudaGetSymbolAddress((void**)&Wqh, g_Wqh); cudaGetSymbolAddress((void**)&Wql, g_Wql);
    cudaGetSymbolAddress((void**)&Wkh, g_Wkh); cudaGetSymbolAddress((void**)&Wkl, g_Wkl);
    cudaGetSymbolAddress((void**)&Wvh, g_Wvh); cudaGetSymbolAddress((void**)&Wvl, g_Wvl);
    cudaGetSymbolAddress((void**)&Qph, g_Qph); cudaGetSymbolAddress((void**)&Qpl, g_Qpl);
    cudaGetSymbolAddress((void**)&Kph, g_Kph); cudaGetSymbolAddress((void**)&Kpl, g_Kpl);
    cudaGetSymbolAddress((void**)&VpT, g_VpT);
    cudaGetSymbolAddress((void**)&S,   g_S);
    cudaGetSymbolAddress((void**)&P,   g_P);

    const int SM_SPLIT  = 3 * 4 * OPB;  // 98304
    const int SM_SINGLE = 6 * 2 * OPB;  // 98304
    cudaFuncSetAttribute(gemm_proj, cudaFuncAttributeMaxDynamicSharedMemorySize, SM_SPLIT);
    cudaFuncSetAttribute(gemm_sv,   cudaFuncAttributeMaxDynamicSharedMemorySize, SM_SPLIT);
    cudaFuncSetAttribute(gemm_pv,   cudaFuncAttributeMaxDynamicSharedMemorySize, SM_SINGLE);

    int n4 = BB * SQL * DDIM / 4;
    cvt_split3<<<dim3(n4 / 256, 3), 256>>>(q, qh, ql, k, kh, kl, v, vh, vl);
    wtrans3<<<dim3(32, 32, 3), dim3(32, 8)>>>(Wq, Wqh, Wql, Wk, Wkh, Wkl, Wv, Wvh, Wvl);

    // Q & K projections: M=16384, N=1024, K=1024 (3-pass split)
    ProjSet pq{qh, ql, Wqh, Wql, Qph, Qpl, bq};
    ProjSet pk{kh, kl, Wkh, Wkl, Kph, Kpl, bk};
    gemm_proj<<<dim3(8, 128, 2), 256, SM_SPLIT>>>(pq, pk);

    // Scores (8 batches) + V projection, one launch
    gemm_sv<<<dim3(16, 16, 12), 256, SM_SPLIT>>>(
        Qph, Qpl, Kph, Kpl, S, vh, vl, Wvh, Wvl, VpT, bv);

    // Softmax (+int mask) -> P fp16
    softmax_k<<<BB * SQL, 256>>>(S, mask, P);

    // Output: per batch, O = P · VpT^T (M=2048, N=1024, K=2048)
    gemm_pv<<<dim3(8, 16, BB), 256, SM_SINGLE>>>(P, VpT, (float*)d_out);
}

// round 11
// speedup vs baseline: 1.4018x; 1.4018x over previous
#include <cuda_runtime.h>
#include <cuda_fp16.h>
#include <cstdint>

#define BB 8
#define SQL 2048
#define SKL 2048
#define DDIM 1024

// ---------------- static device scratch (no allocation allowed) ----------------
__device__ __align__(256) __half g_qh [BB * SQL * DDIM];
__device__ __align__(256) __half g_ql [BB * SQL * DDIM];
__device__ __align__(256) __half g_kh [BB * SKL * DDIM];
__device__ __align__(256) __half g_kl [BB * SKL * DDIM];
__device__ __align__(256) __half g_vh [BB * SKL * DDIM];
__device__ __align__(256) __half g_vl [BB * SKL * DDIM];
__device__ __align__(256) __half g_Wqh[DDIM * DDIM];
__device__ __align__(256) __half g_Wql[DDIM * DDIM];
__device__ __align__(256) __half g_Wkh[DDIM * DDIM];
__device__ __align__(256) __half g_Wkl[DDIM * DDIM];
__device__ __align__(256) __half g_Wvh[DDIM * DDIM];
__device__ __align__(256) __half g_Wvl[DDIM * DDIM];
__device__ __align__(256) __half g_Qph[BB * SQL * DDIM];
__device__ __align__(256) __half g_Qpl[BB * SQL * DDIM];
__device__ __align__(256) __half g_Kph[BB * SKL * DDIM];
__device__ __align__(256) __half g_Kpl[BB * SKL * DDIM];
__device__ __align__(256) __half g_VpT[DDIM * BB * SKL];   // [dv][b*SK + sk]
__device__ __align__(256) float  g_S  [(size_t)BB * SQL * SKL];
__device__ __align__(256) __half g_P  [(size_t)BB * SQL * SKL];

__device__ __forceinline__ uint32_t smem_u32(const void* p) {
    return (uint32_t)__cvta_generic_to_shared(p);
}

// ---------------- merged fp32 -> (hi,lo) fp16 split convert (y picks tensor) ----
__global__ void cvt_split3(const float* __restrict__ x0, __half* h0, __half* l0,
                           const float* __restrict__ x1, __half* h1, __half* l1,
                           const float* __restrict__ x2, __half* h2, __half* l2) {
    const float* x = (blockIdx.y == 0) ? x0 : (blockIdx.y == 1) ? x1 : x2;
    __half* hi = (blockIdx.y == 0) ? h0 : (blockIdx.y == 1) ? h1 : h2;
    __half* lo = (blockIdx.y == 0) ? l0 : (blockIdx.y == 1) ? l1 : l2;
    int i = blockIdx.x * blockDim.x + threadIdx.x;
    float4 v = ((const float4*)x)[i];
    __half a0 = __float2half_rn(v.x), a1 = __float2half_rn(v.y);
    __half a2 = __float2half_rn(v.z), a3 = __float2half_rn(v.w);
    __half b0 = __float2half_rn(v.x - __half2float(a0));
    __half b1 = __float2half_rn(v.y - __half2float(a1));
    __half b2 = __float2half_rn(v.z - __half2float(a2));
    __half b3 = __float2half_rn(v.w - __half2float(a3));
    ((__half2*)hi)[2 * i + 0] = __halves2half2(a0, a1);
    ((__half2*)hi)[2 * i + 1] = __halves2half2(a2, a3);
    ((__half2*)lo)[2 * i + 0] = __halves2half2(b0, b1);
    ((__half2*)lo)[2 * i + 1] = __halves2half2(b2, b3);
}

// ---------------- merged weight transpose + split (z picks matrix) ----------------
__global__ void wtrans3(const float* __restrict__ W0, __half* T0h, __half* T0l,
                        const float* __restrict__ W1, __half* T1h, __half* T1l,
                        const float* __restrict__ W2, __half* T2h, __half* T2l) {
    const float* W = (blockIdx.z == 0) ? W0 : (blockIdx.z == 1) ? W1 : W2;
    __half* WTh = (blockIdx.z == 0) ? T0h : (blockIdx.z == 1) ? T1h : T2h;
    __half* WTl = (blockIdx.z == 0) ? T0l : (blockIdx.z == 1) ? T1l : T2l;
    __shared__ float tile[32][33];
    int kb = blockIdx.x * 32, nb = blockIdx.y * 32;
    int tx = threadIdx.x, ty = threadIdx.y;
#pragma unroll
    for (int r = 0; r < 4; r++)
        tile[ty + 8 * r][tx] = W[(size_t)(kb + ty + 8 * r) * DDIM + nb + tx];
    __syncthreads();
#pragma unroll
    for (int r = 0; r < 4; r++) {
        float x = tile[tx][ty + 8 * r];
        __half h = __float2half_rn(x);
        size_t o = (size_t)(nb + ty + 8 * r) * DDIM + kb + tx;
        WTh[o] = h;
        WTl[o] = __float2half_rn(x - __half2float(h));
    }
}

// XOR swizzle: 64-byte k-rows (32 halves), 4 chunks of 16B per row.
#define OPB 8192   // bytes per operand tile: 128 rows * 64 B

__device__ __forceinline__ uint32_t swz_off(int row, int chunk) {
    return (uint32_t)(row * 64 + ((chunk ^ ((row >> 1) & 3)) << 4));
}

template <int N> __device__ __forceinline__ void cpwait() {
    asm volatile("cp.async.wait_group %0;\n" ::"n"(N));
}

// =====================================================================
// Shared GEMM core. MODE_CT: 2 = fp32 store; 3 = runtime mode (0: bias +
// hi/lo split store; 1: tanh+bias, transposed fp16 store).
// SPLIT: 3 mma passes (Ah*Bh + Ah*Bl + Al*Bh), fp32 accum.
// =====================================================================
template <int MODE_CT, bool SPLIT>
__device__ __forceinline__ void gemm_core(
    const __half* __restrict__ Ah, const __half* __restrict__ Al,
    const __half* __restrict__ Bh, const __half* __restrict__ Bl,
    void* __restrict__ C0b, void* __restrict__ C1b,
    const float* __restrict__ bias,
    int K, int lda, int ldb, int ldc, int rtmode, char* smem) {
    constexpr int NSTG = SPLIT ? 3 : 6;
    constexpr int NAR  = SPLIT ? 4 : 2;
    constexpr int STGB = NAR * OPB;

    const int tid  = threadIdx.x;
    const int lane = tid & 31;
    const int warp = tid >> 5;
    const int wm = warp & 1;
    const int wn = warp >> 1;
    const int gm = blockIdx.y * 128;
    const int gn = blockIdx.x * 128;
    const int nk = K >> 5;

    float c[4][4][4];
#pragma unroll
    for (int i = 0; i < 4; i++)
#pragma unroll
        for (int j = 0; j < 4; j++)
#pragma unroll
            for (int r = 0; r < 4; r++) c[i][j][r] = 0.f;

    auto load_stage = [&](int s, int kt) {
        if (kt < nk) {
            char* stg = smem + s * STGB;
            const int k0 = kt * 32;
#pragma unroll
            for (int op = 0; op < NAR; op++) {
                const __half* base;
                int r0, ld;
                if (SPLIT) {
                    base = (op == 0) ? Ah : (op == 1) ? Al : (op == 2) ? Bh : Bl;
                    r0 = (op < 2) ? gm : gn;
                    ld = (op < 2) ? lda : ldb;
                } else {
                    base = (op == 0) ? Ah : Bh;
                    r0 = (op == 0) ? gm : gn;
                    ld = (op == 0) ? lda : ldb;
                }
                char* dst0 = stg + op * OPB;
#pragma unroll
                for (int it = 0; it < 2; it++) {
                    int qq = tid + it * 256;
                    int r = qq >> 2, cc = qq & 3;
                    uint32_t dst = smem_u32(dst0 + swz_off(r, cc));
                    const __half* src = base + (size_t)(r0 + r) * ld + k0 + cc * 8;
                    asm volatile("cp.async.cg.shared.global [%0], [%1], 16;\n"
                                 ::"r"(dst), "l"(src));
                }
            }
        }
        asm volatile("cp.async.commit_group;\n");
    };

#pragma unroll
    for (int t = 0; t < NSTG - 1; t++) load_stage(t, t);

    uint32_t ah[4][4], al[4][4], bh[4][2], bl[4][2];

    auto load_frags = [&](const char* stg, int ks) {
        const char* sa = stg;
        const char* sb = stg + (SPLIT ? 2 : 1) * OPB;
#pragma unroll
        for (int i = 0; i < 4; i++) {
            int row = wm * 64 + i * 16 + (lane & 15);
            uint32_t o = swz_off(row, ks * 2 + (lane >> 4));
            uint32_t a0 = smem_u32(sa + o);
            asm volatile("ldmatrix.sync.aligned.m8n8.x4.shared.b16 {%0,%1,%2,%3}, [%4];"
                         : "=r"(ah[i][0]), "=r"(ah[i][1]), "=r"(ah[i][2]), "=r"(ah[i][3])
                         : "r"(a0));
            if (SPLIT) {
                uint32_t a1 = smem_u32(sa + OPB + o);
                asm volatile("ldmatrix.sync.aligned.m8n8.x4.shared.b16 {%0,%1,%2,%3}, [%4];"
                             : "=r"(al[i][0]), "=r"(al[i][1]), "=r"(al[i][2]), "=r"(al[i][3])
                             : "r"(a1));
            }
        }
        // B via x4: lanes 0-7 -> (j,k0), 8-15 -> (j,k1), 16-23 -> (j+1,k0), 24-31 -> (j+1,k1)
#pragma unroll
        for (int j = 0; j < 4; j += 2) {
            int row = wn * 32 + (j + (lane >> 4)) * 8 + (lane & 7);
            uint32_t o = swz_off(row, ks * 2 + ((lane >> 3) & 1));
            uint32_t b0 = smem_u32(sb + o);
            asm volatile("ldmatrix.sync.aligned.m8n8.x4.shared.b16 {%0,%1,%2,%3}, [%4];"
                         : "=r"(bh[j][0]), "=r"(bh[j][1]), "=r"(bh[j + 1][0]), "=r"(bh[j + 1][1])
                         : "r"(b0));
            if (SPLIT) {
                uint32_t b1 = smem_u32(sb + OPB + o);
                asm volatile("ldmatrix.sync.aligned.m8n8.x4.shared.b16 {%0,%1,%2,%3}, [%4];"
                             : "=r"(bl[j][0]), "=r"(bl[j][1]), "=r"(bl[j + 1][0]), "=r"(bl[j + 1][1])
                             : "r"(b1));
            }
        }
    };

#define MMA16(AA, BB_)                                                                       \
    asm volatile("mma.sync.aligned.m16n8k16.row.col.f32.f16.f16.f32 "                        \
                 "{%0,%1,%2,%3}, {%4,%5,%6,%7}, {%8,%9}, {%0,%1,%2,%3};"                     \
                 : "+f"(c[i][j][0]), "+f"(c[i][j][1]), "+f"(c[i][j][2]), "+f"(c[i][j][3])    \
                 : "r"(AA[i][0]), "r"(AA[i][1]), "r"(AA[i][2]), "r"(AA[i][3]),               \
                   "r"(BB_[j][0]), "r"(BB_[j][1]))

    auto domma = [&]() {
#pragma unroll
        for (int i = 0; i < 4; i++)
#pragma unroll
            for (int j = 0; j < 4; j++) MMA16(ah, bh);
        if (SPLIT) {
#pragma unroll
            for (int i = 0; i < 4; i++)
#pragma unroll
                for (int j = 0; j < 4; j++) MMA16(ah, bl);
#pragma unroll
            for (int i = 0; i < 4; i++)
#pragma unroll
                for (int j = 0; j < 4; j++) MMA16(al, bh);
        }
    };
#undef MMA16

    for (int kt = 0; kt < nk; kt++) {
        cpwait<NSTG - 2>();
        __syncthreads();
        const char* stg = smem + (kt % NSTG) * STGB;
        load_frags(stg, 0);
        load_stage((kt + NSTG - 1) % NSTG, kt + NSTG - 1);
        domma();
        load_frags(stg, 1);
        domma();
    }

    __syncthreads();

    if (MODE_CT == 2) {
        float* C = (float*)C0b;
#pragma unroll
        for (int i = 0; i < 4; i++)
#pragma unroll
            for (int j = 0; j < 4; j++) {
                int row = gm + wm * 64 + i * 16 + (lane >> 2);
                int col = gn + wn * 32 + j * 8 + ((lane & 3) << 1);
                float2 v0; v0.x = c[i][j][0]; v0.y = c[i][j][1];
                float2 v1; v1.x = c[i][j][2]; v1.y = c[i][j][3];
                *(float2*)(C + (size_t)row * ldc + col) = v0;
                *(float2*)(C + (size_t)(row + 8) * ldc + col) = v1;
            }
    } else {
        if (rtmode == 0) {
            __half* Chi = (__half*)C0b;
            __half* Clo = (__half*)C1b;
#pragma unroll
            for (int i = 0; i < 4; i++)
#pragma unroll
                for (int j = 0; j < 4; j++) {
                    int row = gm + wm * 64 + i * 16 + (lane >> 2);
                    int col = gn + wn * 32 + j * 8 + ((lane & 3) << 1);
                    float b0 = bias[col], b1 = bias[col + 1];
#pragma unroll
                    for (int h = 0; h < 2; h++) {
                        float v0 = c[i][j][2 * h + 0] + b0;
                        float v1 = c[i][j][2 * h + 1] + b1;
                        __half h0 = __float2half_rn(v0), h1 = __float2half_rn(v1);
                        __half l0 = __float2half_rn(v0 - __half2float(h0));
                        __half l1 = __float2half_rn(v1 - __half2float(h1));
                        size_t o = (size_t)(row + 8 * h) * ldc + col;
                        *(__half2*)(Chi + o) = __halves2half2(h0, h1);
                        *(__half2*)(Clo + o) = __halves2half2(l0, l1);
                    }
                }
        } else {  // tanh + transposed fp16 store via smem staging
            __half* st = (__half*)smem;  // 128*136 halves = 34816 B
#pragma unroll
            for (int i = 0; i < 4; i++)
#pragma unroll
                for (int j = 0; j < 4; j++) {
                    int row = wm * 64 + i * 16 + (lane >> 2);
                    int col = wn * 32 + j * 8 + ((lane & 3) << 1);
                    float b0 = bias[gn + col], b1 = bias[gn + col + 1];
                    st[(col + 0) * 136 + row + 0] = __float2half_rn(tanhf(c[i][j][0] + b0));
                    st[(col + 1) * 136 + row + 0] = __float2half_rn(tanhf(c[i][j][1] + b1));
                    st[(col + 0) * 136 + row + 8] = __float2half_rn(tanhf(c[i][j][2] + b0));
                    st[(col + 1) * 136 + row + 8] = __float2half_rn(tanhf(c[i][j][3] + b1));
                }
            __syncthreads();
            __half* C = (__half*)C0b;
            for (int qq = tid; qq < 128 * 128 / 8; qq += 256) {
                int n = qq >> 4, m = (qq & 15) << 3;
                *(uint4*)(C + (size_t)(gn + n) * ldc + gm + m) = *(const uint4*)(st + n * 136 + m);
            }
        }
    }
}

// --------- batched GEMM wrapper (scores / PV), fp32 store ---------
template <bool SPLIT>
__global__ void __launch_bounds__(256, 2)
gemm_b(const __half* __restrict__ Ah_, const __half* __restrict__ Al_,
       const __half* __restrict__ Bh_, const __half* __restrict__ Bl_,
       void* __restrict__ C0b, int K, int lda, int ldb, int ldc,
       long sA, long sB, long sC) {
    extern __shared__ __align__(128) char smem[];
    const __half* Ah = Ah_ + (size_t)blockIdx.z * sA;
    const __half* Al = SPLIT ? (Al_ + (size_t)blockIdx.z * sA) : nullptr;
    const __half* Bh = Bh_ + (size_t)blockIdx.z * sB;
    const __half* Bl = SPLIT ? (Bl_ + (size_t)blockIdx.z * sB) : nullptr;
    float* C = (float*)C0b + (size_t)blockIdx.z * sC;
    gemm_core<2, SPLIT>(Ah, Al, Bh, Bl, C, nullptr, nullptr, K, lda, ldb, ldc, 2, smem);
}

// --------- merged projection kernel: z picks {Q, K, V} ---------
struct ProjSet {
    const __half *Ah, *Al, *Bh, *Bl;
    __half *C0, *C1;
    const float* bias;
    int ldc, mode;
};

__global__ void __launch_bounds__(256, 2)
gemm_proj(ProjSet p0, ProjSet p1, ProjSet p2) {
    extern __shared__ __align__(128) char smem[];
    const ProjSet& p = (blockIdx.z == 0) ? p0 : (blockIdx.z == 1) ? p1 : p2;
    gemm_core<3, true>(p.Ah, p.Al, p.Bh, p.Bl, p.C0, p.C1, p.bias,
                       DDIM, DDIM, DDIM, p.ldc, p.mode, smem);
}

// ---------------- vectorized softmax (+ int32 bool-mask add) -> fp16 P ----------------
__global__ void softmax_k(const float* __restrict__ S, const int* __restrict__ mask,
                          __half* __restrict__ P) {
    int row = blockIdx.x;
    int b = row >> 11;
    int t = threadIdx.x;
    const float4* s4 = (const float4*)(S + (size_t)row * SKL);
    const int4*   m4 = (const int4*)(mask + (size_t)b * SKL);

    float4 v[2];
    float mx = -3.4e38f;
#pragma unroll
    for (int i = 0; i < 2; i++) {
        float4 sv = s4[t + i * 256];
        int4 mv = m4[t + i * 256];
        sv.x += mv.x ? 1.0f : 0.0f;
        sv.y += mv.y ? 1.0f : 0.0f;
        sv.z += mv.z ? 1.0f : 0.0f;
        sv.w += mv.w ? 1.0f : 0.0f;
        v[i] = sv;
        mx = fmaxf(mx, fmaxf(fmaxf(sv.x, sv.y), fmaxf(sv.z, sv.w)));
    }
    __shared__ float red[8];
#pragma unroll
    for (int o = 16; o > 0; o >>= 1) mx = fmaxf(mx, __shfl_xor_sync(0xffffffffu, mx, o));
    if ((t & 31) == 0) red[t >> 5] = mx;
    __syncthreads();
    mx = red[0];
#pragma unroll
    for (int i = 1; i < 8; i++) mx = fmaxf(mx, red[i]);
    __syncthreads();

    float sum = 0.f;
#pragma unroll
    for (int i = 0; i < 2; i++) {
        v[i].x = __expf(v[i].x - mx);
        v[i].y = __expf(v[i].y - mx);
        v[i].z = __expf(v[i].z - mx);
        v[i].w = __expf(v[i].w - mx);
        sum += v[i].x + v[i].y + v[i].z + v[i].w;
    }
#pragma unroll
    for (int o = 16; o > 0; o >>= 1) sum += __shfl_xor_sync(0xffffffffu, sum, o);
    if ((t & 31) == 0) red[t >> 5] = sum;
    __syncthreads();
    sum = red[0];
#pragma unroll
    for (int i = 1; i < 8; i++) sum += red[i];

    float inv = 1.0f / sum;
    __half* Pr = P + (size_t)row * SKL;
#pragma unroll
    for (int i = 0; i < 2; i++) {
        __half2 h0 = __floats2half2_rn(v[i].x * inv, v[i].y * inv);
        __half2 h1 = __floats2half2_rn(v[i].z * inv, v[i].w * inv);
        uint2 pk;
        pk.x = *(uint32_t*)&h0;
        pk.y = *(uint32_t*)&h1;
        *(uint2*)(Pr + 4 * (t + i * 256)) = pk;
    }
}

// ---------------- launch ----------------
extern "C" void kernel_launch(void* const* d_in, const int* in_sizes, int n_in,
                              void* d_out, int out_size) {
    const float* q  = (const float*)d_in[0];
    const float* k  = (const float*)d_in[1];
    const float* v  = (const float*)d_in[2];
    const int*   mask = (const int*)d_in[3];
    const float* Wq = (const float*)d_in[4];
    const float* bq = (const float*)d_in[5];
    const float* Wk = (const float*)d_in[6];
    const float* bk = (const float*)d_in[7];
    const float* Wv = (const float*)d_in[8];
    const float* bv = (const float*)d_in[9];

    __half *qh, *ql, *kh, *kl, *vh, *vl;
    __half *Wqh, *Wql, *Wkh, *Wkl, *Wvh, *Wvl;
    __half *Qph, *Qpl, *Kph, *Kpl, *VpT, *P;
    float* S;
    cudaGetSymbolAddress((void**)&qh,  g_qh);  cudaGetSymbolAddress((void**)&ql,  g_ql);
    cudaGetSymbolAddress((void**)&kh,  g_kh);  cudaGetSymbolAddress((void**)&kl,  g_kl);
    cudaGetSymbolAddress((void**)&vh,  g_vh);  cudaGetSymbolAddress((void**)&vl,  g_vl);
    cudaGetSymbolAddress((void**)&Wqh, g_Wqh); cudaGetSymbolAddress((void**)&Wql, g_Wql);
    cudaGetSymbolAddress((void**)&Wkh, g_Wkh); cudaGetSymbolAddress((void**)&Wkl, g_Wkl);
    cudaGetSymbolAddress((void**)&Wvh, g_Wvh); cudaGetSymbolAddress((void**)&Wvl, g_Wvl);
    cudaGetSymbolAddress((void**)&Qph, g_Qph); cudaGetSymbolAddress((void**)&Qpl, g_Qpl);
    cudaGetSymbolAddress((void**)&Kph, g_Kph); cudaGetSymbolAddress((void**)&Kpl, g_Kpl);
    cudaGetSymbolAddress((void**)&VpT, g_VpT);
    cudaGetSymbolAddress((void**)&S,   g_S);
    cudaGetSymbolAddress((void**)&P,   g_P);

    const int SM_SPLIT  = 3 * 4 * OPB;  // 98304
    const int SM_SINGLE = 6 * 2 * OPB;  // 98304
    cudaFuncSetAttribute(gemm_proj,     cudaFuncAttributeMaxDynamicSharedMemorySize, SM_SPLIT);
    cudaFuncSetAttribute(gemm_b<true>,  cudaFuncAttributeMaxDynamicSharedMemorySize, SM_SPLIT);
    cudaFuncSetAttribute(gemm_b<false>, cudaFuncAttributeMaxDynamicSharedMemorySize, SM_SINGLE);

    int n4 = BB * SQL * DDIM / 4;
    cvt_split3<<<dim3(n4 / 256, 3), 256>>>(q, qh, ql, k, kh, kl, v, vh, vl);

    wtrans3<<<dim3(32, 32, 3), dim3(32, 8)>>>(Wq, Wqh, Wql, Wk, Wkh, Wkl, Wv, Wvh, Wvl);

    // All 3 projections in one launch: M=16384, N=1024, K=1024 (3-pass split)
    ProjSet pq{qh, ql, Wqh, Wql, Qph, Qpl, bq, 1024, 0};
    ProjSet pk{kh, kl, Wkh, Wkl, Kph, Kpl, bk, 1024, 0};
    ProjSet pv{vh, vl, Wvh, Wvl, VpT, nullptr, bv, BB * SKL, 1};
    gemm_proj<<<dim3(8, 128, 3), 256, SM_SPLIT>>>(pq, pk, pv);

    // Scores: per batch, S = Qp Kp^T (M=N=2048, K=1024), 3-pass split
    gemm_b<true><<<dim3(16, 16, BB), 256, SM_SPLIT>>>(
        Qph, Qpl, Kph, Kpl, S, 1024, 1024, 1024, 2048,
        (long)SQL * DDIM, (long)SKL * DDIM, (long)SQL * SKL);

    // Softmax (+int mask) -> P fp16
    softmax_k<<<BB * SQL, 256>>>(S, mask, P);

    // Output: per batch, O = P · VpT^T (M=2048, N=1024, K=2048), single-pass fp16
    gemm_b<false><<<dim3(8, 16, BB), 256, SM_SINGLE>>>(
        P, nullptr, VpT, nullptr, d_out, 2048, 2048, BB * SKL, 1024,
        (long)SQL * SKL, (long)SKL, (long)SQL * DDIM);
}

// round 13
// speedup vs baseline: 1.4702x; 1.0488x over previous
#include <cuda_runtime.h>
#include <cuda_fp16.h>
#include <cstdint>

#define BB 8
#define SQL 2048
#define SKL 2048
#define DDIM 1024

// ---------------- static device scratch (no allocation allowed) ----------------
__device__ __align__(256) __half g_qh [BB * SQL * DDIM];
__device__ __align__(256) __half g_ql [BB * SQL * DDIM];
__device__ __align__(256) __half g_kh [BB * SKL * DDIM];
__device__ __align__(256) __half g_kl [BB * SKL * DDIM];
__device__ __align__(256) __half g_vh [BB * SKL * DDIM];
__device__ __align__(256) __half g_vl [BB * SKL * DDIM];
__device__ __align__(256) __half g_Wqh[DDIM * DDIM];
__device__ __align__(256) __half g_Wql[DDIM * DDIM];
__device__ __align__(256) __half g_Wkh[DDIM * DDIM];
__device__ __align__(256) __half g_Wkl[DDIM * DDIM];
__device__ __align__(256) __half g_Wvh[DDIM * DDIM];
__device__ __align__(256) __half g_Wvl[DDIM * DDIM];
__device__ __align__(256) __half g_Qph[BB * SQL * DDIM];
__device__ __align__(256) __half g_Qpl[BB * SQL * DDIM];
__device__ __align__(256) __half g_Kph[BB * SKL * DDIM];
__device__ __align__(256) __half g_Kpl[BB * SKL * DDIM];
__device__ __align__(256) __half g_VpT[DDIM * BB * SKL];   // [dv][b*SK + sk]
__device__ __align__(256) float  g_S  [(size_t)BB * SQL * SKL];
__device__ __align__(256) __half g_P  [(size_t)BB * SQL * SKL];

__device__ __forceinline__ uint32_t smem_u32(const void* p) {
    return (uint32_t)__cvta_generic_to_shared(p);
}

// ---------------- merged fp32 -> (hi,lo) fp16 split convert (y picks tensor) ----
__global__ void cvt_split3(const float* __restrict__ x0, __half* h0, __half* l0,
                           const float* __restrict__ x1, __half* h1, __half* l1,
                           const float* __restrict__ x2, __half* h2, __half* l2) {
    const float* x = (blockIdx.y == 0) ? x0 : (blockIdx.y == 1) ? x1 : x2;
    __half* hi = (blockIdx.y == 0) ? h0 : (blockIdx.y == 1) ? h1 : h2;
    __half* lo = (blockIdx.y == 0) ? l0 : (blockIdx.y == 1) ? l1 : l2;
    int i = blockIdx.x * blockDim.x + threadIdx.x;
    float4 v = ((const float4*)x)[i];
    __half a0 = __float2half_rn(v.x), a1 = __float2half_rn(v.y);
    __half a2 = __float2half_rn(v.z), a3 = __float2half_rn(v.w);
    __half b0 = __float2half_rn(v.x - __half2float(a0));
    __half b1 = __float2half_rn(v.y - __half2float(a1));
    __half b2 = __float2half_rn(v.z - __half2float(a2));
    __half b3 = __float2half_rn(v.w - __half2float(a3));
    ((__half2*)hi)[2 * i + 0] = __halves2half2(a0, a1);
    ((__half2*)hi)[2 * i + 1] = __halves2half2(a2, a3);
    ((__half2*)lo)[2 * i + 0] = __halves2half2(b0, b1);
    ((__half2*)lo)[2 * i + 1] = __halves2half2(b2, b3);
}

// ---------------- merged weight transpose + split (z picks matrix) ----------------
__global__ void wtrans3(const float* __restrict__ W0, __half* T0h, __half* T0l,
                        const float* __restrict__ W1, __half* T1h, __half* T1l,
                        const float* __restrict__ W2, __half* T2h, __half* T2l) {
    const float* W = (blockIdx.z == 0) ? W0 : (blockIdx.z == 1) ? W1 : W2;
    __half* WTh = (blockIdx.z == 0) ? T0h : (blockIdx.z == 1) ? T1h : T2h;
    __half* WTl = (blockIdx.z == 0) ? T0l : (blockIdx.z == 1) ? T1l : T2l;
    __shared__ float tile[32][33];
    int kb = blockIdx.x * 32, nb = blockIdx.y * 32;
    int tx = threadIdx.x, ty = threadIdx.y;
#pragma unroll
    for (int r = 0; r < 4; r++)
        tile[ty + 8 * r][tx] = W[(size_t)(kb + ty + 8 * r) * DDIM + nb + tx];
    __syncthreads();
#pragma unroll
    for (int r = 0; r < 4; r++) {
        float x = tile[tx][ty + 8 * r];
        __half h = __float2half_rn(x);
        size_t o = (size_t)(nb + ty + 8 * r) * DDIM + kb + tx;
        WTh[o] = h;
        WTl[o] = __float2half_rn(x - __half2float(h));
    }
}

// XOR swizzle: 64-byte k-rows (32 halves), 4 chunks of 16B per row.
#define OPB 8192   // bytes per operand tile: 128 rows * 64 B

__device__ __forceinline__ uint32_t swz_off(int row, int chunk) {
    return (uint32_t)(row * 64 + ((chunk ^ ((row >> 1) & 3)) << 4));
}

template <int N> __device__ __forceinline__ void cpwait() {
    asm volatile("cp.async.wait_group %0;\n" ::"n"(N));
}

// =====================================================================
// Shared GEMM core. MODE_CT: 2 = fp32 store; 3 = runtime mode (0: bias +
// hi/lo split store; 1: tanh+bias, transposed fp16 store).
// SPLIT: 3 mma passes (Ah*Bh + Ah*Bl + Al*Bh), fp32 accum.
// =====================================================================
template <int MODE_CT, bool SPLIT>
__device__ __forceinline__ void gemm_core(
    const __half* __restrict__ Ah, const __half* __restrict__ Al,
    const __half* __restrict__ Bh, const __half* __restrict__ Bl,
    void* __restrict__ C0b, void* __restrict__ C1b,
    const float* __restrict__ bias,
    int K, int lda, int ldb, int ldc, int gm, int gn, int rtmode, char* smem) {
    constexpr int NSTG = SPLIT ? 3 : 6;
    constexpr int NAR  = SPLIT ? 4 : 2;
    constexpr int STGB = NAR * OPB;

    const int tid  = threadIdx.x;
    const int lane = tid & 31;
    const int warp = tid >> 5;
    const int wm = warp & 1;
    const int wn = warp >> 1;
    const int nk = K >> 5;

    float c[4][4][4];
#pragma unroll
    for (int i = 0; i < 4; i++)
#pragma unroll
        for (int j = 0; j < 4; j++)
#pragma unroll
            for (int r = 0; r < 4; r++) c[i][j][r] = 0.f;

    auto load_stage = [&](int s, int kt) {
        if (kt < nk) {
            char* stg = smem + s * STGB;
            const int k0 = kt * 32;
#pragma unroll
            for (int op = 0; op < NAR; op++) {
                const __half* base;
                int r0, ld;
                if (SPLIT) {
                    base = (op == 0) ? Ah : (op == 1) ? Al : (op == 2) ? Bh : Bl;
                    r0 = (op < 2) ? gm : gn;
                    ld = (op < 2) ? lda : ldb;
                } else {
                    base = (op == 0) ? Ah : Bh;
                    r0 = (op == 0) ? gm : gn;
                    ld = (op == 0) ? lda : ldb;
                }
                char* dst0 = stg + op * OPB;
#pragma unroll
                for (int it = 0; it < 2; it++) {
                    int qq = tid + it * 256;
                    int r = qq >> 2, cc = qq & 3;
                    uint32_t dst = smem_u32(dst0 + swz_off(r, cc));
                    const __half* src = base + (size_t)(r0 + r) * ld + k0 + cc * 8;
                    asm volatile("cp.async.cg.shared.global [%0], [%1], 16;\n"
                                 ::"r"(dst), "l"(src));
                }
            }
        }
        asm volatile("cp.async.commit_group;\n");
    };

#pragma unroll
    for (int t = 0; t < NSTG - 1; t++) load_stage(t, t);

    uint32_t ah[4][4], al[4][4], bh[4][2], bl[4][2];

    auto load_frags = [&](const char* stg, int ks) {
        const char* sa = stg;
        const char* sb = stg + (SPLIT ? 2 : 1) * OPB;
#pragma unroll
        for (int i = 0; i < 4; i++) {
            int row = wm * 64 + i * 16 + (lane & 15);
            uint32_t o = swz_off(row, ks * 2 + (lane >> 4));
            uint32_t a0 = smem_u32(sa + o);
            asm volatile("ldmatrix.sync.aligned.m8n8.x4.shared.b16 {%0,%1,%2,%3}, [%4];"
                         : "=r"(ah[i][0]), "=r"(ah[i][1]), "=r"(ah[i][2]), "=r"(ah[i][3])
                         : "r"(a0));
            if (SPLIT) {
                uint32_t a1 = smem_u32(sa + OPB + o);
                asm volatile("ldmatrix.sync.aligned.m8n8.x4.shared.b16 {%0,%1,%2,%3}, [%4];"
                             : "=r"(al[i][0]), "=r"(al[i][1]), "=r"(al[i][2]), "=r"(al[i][3])
                             : "r"(a1));
            }
        }
        // B via x4: lanes 0-7 -> (j,k0), 8-15 -> (j,k1), 16-23 -> (j+1,k0), 24-31 -> (j+1,k1)
#pragma unroll
        for (int j = 0; j < 4; j += 2) {
            int row = wn * 32 + (j + (lane >> 4)) * 8 + (lane & 7);
            uint32_t o = swz_off(row, ks * 2 + ((lane >> 3) & 1));
            uint32_t b0 = smem_u32(sb + o);
            asm volatile("ldmatrix.sync.aligned.m8n8.x4.shared.b16 {%0,%1,%2,%3}, [%4];"
                         : "=r"(bh[j][0]), "=r"(bh[j][1]), "=r"(bh[j + 1][0]), "=r"(bh[j + 1][1])
                         : "r"(b0));
            if (SPLIT) {
                uint32_t b1 = smem_u32(sb + OPB + o);
                asm volatile("ldmatrix.sync.aligned.m8n8.x4.shared.b16 {%0,%1,%2,%3}, [%4];"
                             : "=r"(bl[j][0]), "=r"(bl[j][1]), "=r"(bl[j + 1][0]), "=r"(bl[j + 1][1])
                             : "r"(b1));
            }
        }
    };

#define MMA16(AA, BB_)                                                                       \
    asm volatile("mma.sync.aligned.m16n8k16.row.col.f32.f16.f16.f32 "                        \
                 "{%0,%1,%2,%3}, {%4,%5,%6,%7}, {%8,%9}, {%0,%1,%2,%3};"                     \
                 : "+f"(c[i][j][0]), "+f"(c[i][j][1]), "+f"(c[i][j][2]), "+f"(c[i][j][3])    \
                 : "r"(AA[i][0]), "r"(AA[i][1]), "r"(AA[i][2]), "r"(AA[i][3]),               \
                   "r"(BB_[j][0]), "r"(BB_[j][1]))

    auto domma = [&]() {
#pragma unroll
        for (int i = 0; i < 4; i++)
#pragma unroll
            for (int j = 0; j < 4; j++) MMA16(ah, bh);
        if (SPLIT) {
#pragma unroll
            for (int i = 0; i < 4; i++)
#pragma unroll
                for (int j = 0; j < 4; j++) MMA16(ah, bl);
#pragma unroll
            for (int i = 0; i < 4; i++)
#pragma unroll
                for (int j = 0; j < 4; j++) MMA16(al, bh);
        }
    };
#undef MMA16

    for (int kt = 0; kt < nk; kt++) {
        cpwait<NSTG - 2>();
        __syncthreads();
        const char* stg = smem + (kt % NSTG) * STGB;
        load_frags(stg, 0);
        load_stage((kt + NSTG - 1) % NSTG, kt + NSTG - 1);
        domma();
        load_frags(stg, 1);
        domma();
    }

    __syncthreads();

    if (MODE_CT == 2) {
        float* C = (float*)C0b;
#pragma unroll
        for (int i = 0; i < 4; i++)
#pragma unroll
            for (int j = 0; j < 4; j++) {
                int row = gm + wm * 64 + i * 16 + (lane >> 2);
                int col = gn + wn * 32 + j * 8 + ((lane & 3) << 1);
                float2 v0; v0.x = c[i][j][0]; v0.y = c[i][j][1];
                float2 v1; v1.x = c[i][j][2]; v1.y = c[i][j][3];
                *(float2*)(C + (size_t)row * ldc + col) = v0;
                *(float2*)(C + (size_t)(row + 8) * ldc + col) = v1;
            }
    } else {
        if (rtmode == 0) {
            __half* Chi = (__half*)C0b;
            __half* Clo = (__half*)C1b;
#pragma unroll
            for (int i = 0; i < 4; i++)
#pragma unroll
                for (int j = 0; j < 4; j++) {
                    int row = gm + wm * 64 + i * 16 + (lane >> 2);
                    int col = gn + wn * 32 + j * 8 + ((lane & 3) << 1);
                    float b0 = bias[col], b1 = bias[col + 1];
#pragma unroll
                    for (int h = 0; h < 2; h++) {
                        float v0 = c[i][j][2 * h + 0] + b0;
                        float v1 = c[i][j][2 * h + 1] + b1;
                        __half h0 = __float2half_rn(v0), h1 = __float2half_rn(v1);
                        __half l0 = __float2half_rn(v0 - __half2float(h0));
                        __half l1 = __float2half_rn(v1 - __half2float(h1));
                        size_t o = (size_t)(row + 8 * h) * ldc + col;
                        *(__half2*)(Chi + o) = __halves2half2(h0, h1);
                        *(__half2*)(Clo + o) = __halves2half2(l0, l1);
                    }
                }
        } else {  // tanh + transposed fp16 store via smem staging
            __half* st = (__half*)smem;  // 128*136 halves = 34816 B
#pragma unroll
            for (int i = 0; i < 4; i++)
#pragma unroll
                for (int j = 0; j < 4; j++) {
                    int row = wm * 64 + i * 16 + (lane >> 2);
                    int col = wn * 32 + j * 8 + ((lane & 3) << 1);
                    float b0 = bias[gn + col], b1 = bias[gn + col + 1];
                    st[(col + 0) * 136 + row + 0] = __float2half_rn(tanhf(c[i][j][0] + b0));
                    st[(col + 1) * 136 + row + 0] = __float2half_rn(tanhf(c[i][j][1] + b1));
                    st[(col + 0) * 136 + row + 8] = __float2half_rn(tanhf(c[i][j][2] + b0));
                    st[(col + 1) * 136 + row + 8] = __float2half_rn(tanhf(c[i][j][3] + b1));
                }
            __syncthreads();
            __half* C = (__half*)C0b;
            for (int qq = tid; qq < 128 * 128 / 8; qq += 256) {
                int n = qq >> 4, m = (qq & 15) << 3;
                *(uint4*)(C + (size_t)(gn + n) * ldc + gm + m) = *(const uint4*)(st + n * 136 + m);
            }
        }
    }
}

// --------- projection kernel: z picks {Q, K} ---------
struct ProjSet {
    const __half *Ah, *Al, *Bh, *Bl;
    __half *C0, *C1;
    const float* bias;
};

__global__ void __launch_bounds__(256, 2)
gemm_proj(ProjSet p0, ProjSet p1) {
    extern __shared__ __align__(128) char smem[];
    const ProjSet& p = (blockIdx.z == 0) ? p0 : p1;
    gemm_core<3, true>(p.Ah, p.Al, p.Bh, p.Bl, p.C0, p.C1, p.bias,
                       DDIM, DDIM, DDIM, DDIM,
                       blockIdx.y * 128, blockIdx.x * 128, 0, smem);
}

// --------- merged V-projection + scores launch ---------
// z in [0,4): V-projection tiles (tanh + transposed store), z-first for backfill
// z in [4,12): scores batch z-4
__global__ void __launch_bounds__(256, 2)
gemm_sv(const __half* Qph, const __half* Qpl, const __half* Kph, const __half* Kpl,
        float* S,
        const __half* vh, const __half* vl, const __half* Wvh, const __half* Wvl,
        __half* VpT, const float* bv) {
    extern __shared__ __align__(128) char smem[];
    int z = blockIdx.z;
    if (z >= 4) {
        int b = z - 4;
        gemm_core<2, true>(Qph + (size_t)b * SQL * DDIM, Qpl + (size_t)b * SQL * DDIM,
                           Kph + (size_t)b * SKL * DDIM, Kpl + (size_t)b * SKL * DDIM,
                           S + (size_t)b * SQL * SKL, nullptr, nullptr,
                           DDIM, DDIM, DDIM, SKL,
                           blockIdx.y * 128, blockIdx.x * 128, 2, smem);
    } else {
        // 4 z-slices x 256 xy-blocks = 1024 tiles of the 16384x1024 V projection
        int t = z * 256 + blockIdx.y * 16 + blockIdx.x;   // 0..1023
        gemm_core<3, true>(vh, vl, Wvh, Wvl, VpT, nullptr, bv,
                           DDIM, DDIM, DDIM, BB * SKL,
                           (t >> 3) * 128, (t & 7) * 128, 1, smem);
    }
}

// --------- PV kernel (single-pass fp16) ---------
__global__ void __launch_bounds__(256, 2)
gemm_pv(const __half* __restrict__ P, const __half* __restrict__ VpT,
        float* __restrict__ O) {
    extern __shared__ __align__(128) char smem[];
    int b = blockIdx.z;
    gemm_core<2, false>(P + (size_t)b * SQL * SKL, nullptr,
                        VpT + (size_t)b * SKL, nullptr,
                        O + (size_t)b * SQL * DDIM, nullptr, nullptr,
                        SKL, SKL, BB * SKL, DDIM,
                        blockIdx.y * 128, blockIdx.x * 128, 2, smem);
}

// ---------------- vectorized softmax (+ int32 bool-mask add) -> fp16 P ----------------
__global__ void softmax_k(const float* __restrict__ S, const int* __restrict__ mask,
                          __half* __restrict__ P) {
    int row = blockIdx.x;
    int b = row >> 11;
    int t = threadIdx.x;
    const float4* s4 = (const float4*)(S + (size_t)row * SKL);
    const int4*   m4 = (const int4*)(mask + (size_t)b * SKL);

    float4 v[2];
    float mx = -3.4e38f;
#pragma unroll
    for (int i = 0; i < 2; i++) {
        float4 sv = s4[t + i * 256];
        int4 mv = m4[t + i * 256];
        sv.x += mv.x ? 1.0f : 0.0f;
        sv.y += mv.y ? 1.0f : 0.0f;
        sv.z += mv.z ? 1.0f : 0.0f;
        sv.w += mv.w ? 1.0f : 0.0f;
        v[i] = sv;
        mx = fmaxf(mx, fmaxf(fmaxf(sv.x, sv.y), fmaxf(sv.z, sv.w)));
    }
    __shared__ float red[8];
#pragma unroll
    for (int o = 16; o > 0; o >>= 1) mx = fmaxf(mx, __shfl_xor_sync(0xffffffffu, mx, o));
    if ((t & 31) == 0) red[t >> 5] = mx;
    __syncthreads();
    mx = red[0];
#pragma unroll
    for (int i = 1; i < 8; i++) mx = fmaxf(mx, red[i]);
    __syncthreads();

    float sum = 0.f;
#pragma unroll
    for (int i = 0; i < 2; i++) {
        v[i].x = __expf(v[i].x - mx);
        v[i].y = __expf(v[i].y - mx);
        v[i].z = __expf(v[i].z - mx);
        v[i].w = __expf(v[i].w - mx);
        sum += v[i].x + v[i].y + v[i].z + v[i].w;
    }
#pragma unroll
    for (int o = 16; o > 0; o >>= 1) sum += __shfl_xor_sync(0xffffffffu, sum, o);
    if ((t & 31) == 0) red[t >> 5] = sum;
    __syncthreads();
    sum = red[0];
#pragma unroll
    for (int i = 1; i < 8; i++) sum += red[i];

    float inv = 1.0f / sum;
    __half* Pr = P + (size_t)row * SKL;
#pragma unroll
    for (int i = 0; i < 2; i++) {
        __half2 h0 = __floats2half2_rn(v[i].x * inv, v[i].y * inv);
        __half2 h1 = __floats2half2_rn(v[i].z * inv, v[i].w * inv);
        uint2 pk;
        pk.x = *(uint32_t*)&h0;
        pk.y = *(uint32_t*)&h1;
        *(uint2*)(Pr + 4 * (t + i * 256)) = pk;
    }
}

// ---------------- launch ----------------
extern "C" void kernel_launch(void* const* d_in, const int* in_sizes, int n_in,
                              void* d_out, int out_size) {
    const float* q  = (const float*)d_in[0];
    const float* k  = (const float*)d_in[1];
    const float* v  = (const float*)d_in[2];
    const int*   mask = (const int*)d_in[3];
    const float* Wq = (const float*)d_in[4];
    const float* bq = (const float*)d_in[5];
    const float* Wk = (const float*)d_in[6];
    const float* bk = (const float*)d_in[7];
    const float* Wv = (const float*)d_in[8];
    const float* bv = (const float*)d_in[9];

    __half *qh, *ql, *kh, *kl, *vh, *vl;
    __half *Wqh, *Wql, *Wkh, *Wkl, *Wvh, *Wvl;
    __half *Qph, *Qpl, *Kph, *Kpl, *VpT, *P;
    float* S;
    cudaGetSymbolAddress((void**)&qh,  g_qh);  cudaGetSymbolAddress((void**)&ql,  g_ql);
    cudaGetSymbolAddress((void**)&kh,  g_kh);  cudaGetSymbolAddress((void**)&kl,  g_kl);
    cudaGetSymbolAddress((void**)&vh,  g_vh);  cudaGetSymbolAddress((void**)&vl,  g_vl);
    cudaGetSymbolAddress((void**)&Wqh, g_Wqh); cudaGetSymbolAddress((void**)&Wql, g_Wql);
    cudaGetSymbolAddress((void**)&Wkh, g_Wkh); cudaGetSymbolAddress((void**)&Wkl, g_Wkl);
    cudaGetSymbolAddress((void**)&Wvh, g_Wvh); cudaGetSymbolAddress((void**)&Wvl, g_Wvl);
    cudaGetSymbolAddress((void**)&Qph, g_Qph); cudaGetSymbolAddress((void**)&Qpl, g_Qpl);
    cudaGetSymbolAddress((void**)&Kph, g_Kph); cudaGetSymbolAddress((void**)&Kpl, g_Kpl);
    cudaGetSymbolAddress((void**)&VpT, g_VpT);
    cudaGetSymbolAddress((void**)&S,   g_S);
    cudaGetSymbolAddress((void**)&P,   g_P);

    const int SM_SPLIT  = 3 * 4 * OPB;  // 98304
    const int SM_SINGLE = 6 * 2 * OPB;  // 98304
    cudaFuncSetAttribute(gemm_proj, cudaFuncAttributeMaxDynamicSharedMemorySize, SM_SPLIT);
    cudaFuncSetAttribute(gemm_sv,   cudaFuncAttributeMaxDynamicSharedMemorySize, SM_SPLIT);
    cudaFuncSetAttribute(gemm_pv,   cudaFuncAttributeMaxDynamicSharedMemorySize, SM_SINGLE);

    int n4 = BB * SQL * DDIM / 4;
    cvt_split3<<<dim3(n4 / 256, 3), 256>>>(q, qh, ql, k, kh, kl, v, vh, vl);

    wtrans3<<<dim3(32, 32, 3), dim3(32, 8)>>>(Wq, Wqh, Wql, Wk, Wkh, Wkl, Wv, Wvh, Wvl);

    // Q & K projections: M=16384, N=1024, K=1024 (3-pass split)
    ProjSet pq{qh, ql, Wqh, Wql, Qph, Qpl, bq};
    ProjSet pk{kh, kl, Wkh, Wkl, Kph, Kpl, bk};
    gemm_proj<<<dim3(8, 128, 2), 256, SM_SPLIT>>>(pq, pk);

    // V projection (z 0-3) + scores for 8 batches (z 4-11), one launch
    gemm_sv<<<dim3(16, 16, 12), 256, SM_SPLIT>>>(
        Qph, Qpl, Kph, Kpl, S, vh, vl, Wvh, Wvl, VpT, bv);

    // Softmax (+int mask) -> P fp16
    softmax_k<<<BB * SQL, 256>>>(S, mask, P);

    // Output: per batch, O = P · VpT^T (M=2048, N=1024, K=2048), single-pass fp16
    gemm_pv<<<dim3(8, 16, BB), 256, SM_SINGLE>>>(P, VpT, (float*)d_out);
}

// round 14
// speedup vs baseline: 1.6072x; 1.0931x over previous
#include <cuda_runtime.h>
#include <cuda_fp16.h>
#include <cstdint>

#define BB 8
#define SQL 2048
#define SKL 2048
#define DDIM 1024

// ---------------- static device scratch (no allocation allowed) ----------------
__device__ __align__(256) __half g_qh [BB * SQL * DDIM];
__device__ __align__(256) __half g_ql [BB * SQL * DDIM];
__device__ __align__(256) __half g_kh [BB * SKL * DDIM];
__device__ __align__(256) __half g_kl [BB * SKL * DDIM];
__device__ __align__(256) __half g_vh [BB * SKL * DDIM];
__device__ __align__(256) __half g_vl [BB * SKL * DDIM];
__device__ __align__(256) __half g_Wqh[DDIM * DDIM];
__device__ __align__(256) __half g_Wql[DDIM * DDIM];
__device__ __align__(256) __half g_Wkh[DDIM * DDIM];
__device__ __align__(256) __half g_Wkl[DDIM * DDIM];
__device__ __align__(256) __half g_Wvh[DDIM * DDIM];
__device__ __align__(256) __half g_Wvl[DDIM * DDIM];
__device__ __align__(256) __half g_Qph[BB * SQL * DDIM];
__device__ __align__(256) __half g_Qpl[BB * SQL * DDIM];
__device__ __align__(256) __half g_Kph[BB * SKL * DDIM];
__device__ __align__(256) __half g_Kpl[BB * SKL * DDIM];
__device__ __align__(256) __half g_VpT[DDIM * BB * SKL];   // [dv][b*SK + sk]
__device__ __align__(256) float  g_S  [(size_t)BB * SQL * SKL];
__device__ __align__(256) __half g_P  [(size_t)BB * SQL * SKL];

__device__ __forceinline__ uint32_t smem_u32(const void* p) {
    return (uint32_t)__cvta_generic_to_shared(p);
}

// ---------------- merged fp32 -> (hi,lo) fp16 split convert (y picks tensor) ----
__global__ void cvt_split3(const float* __restrict__ x0, __half* h0, __half* l0,
                           const float* __restrict__ x1, __half* h1, __half* l1,
                           const float* __restrict__ x2, __half* h2, __half* l2) {
    const float* x = (blockIdx.y == 0) ? x0 : (blockIdx.y == 1) ? x1 : x2;
    __half* hi = (blockIdx.y == 0) ? h0 : (blockIdx.y == 1) ? h1 : h2;
    __half* lo = (blockIdx.y == 0) ? l0 : (blockIdx.y == 1) ? l1 : l2;
    int i = blockIdx.x * blockDim.x + threadIdx.x;
    float4 v = ((const float4*)x)[i];
    __half a0 = __float2half_rn(v.x), a1 = __float2half_rn(v.y);
    __half a2 = __float2half_rn(v.z), a3 = __float2half_rn(v.w);
    __half b0 = __float2half_rn(v.x - __half2float(a0));
    __half b1 = __float2half_rn(v.y - __half2float(a1));
    __half b2 = __float2half_rn(v.z - __half2float(a2));
    __half b3 = __float2half_rn(v.w - __half2float(a3));
    ((__half2*)hi)[2 * i + 0] = __halves2half2(a0, a1);
    ((__half2*)hi)[2 * i + 1] = __halves2half2(a2, a3);
    ((__half2*)lo)[2 * i + 0] = __halves2half2(b0, b1);
    ((__half2*)lo)[2 * i + 1] = __halves2half2(b2, b3);
}

// ---------------- merged weight transpose + split (z picks matrix) ----------------
__global__ void wtrans3(const float* __restrict__ W0, __half* T0h, __half* T0l,
                        const float* __restrict__ W1, __half* T1h, __half* T1l,
                        const float* __restrict__ W2, __half* T2h, __half* T2l) {
    const float* W = (blockIdx.z == 0) ? W0 : (blockIdx.z == 1) ? W1 : W2;
    __half* WTh = (blockIdx.z == 0) ? T0h : (blockIdx.z == 1) ? T1h : T2h;
    __half* WTl = (blockIdx.z == 0) ? T0l : (blockIdx.z == 1) ? T1l : T2l;
    __shared__ float tile[32][33];
    int kb = blockIdx.x * 32, nb = blockIdx.y * 32;
    int tx = threadIdx.x, ty = threadIdx.y;
#pragma unroll
    for (int r = 0; r < 4; r++)
        tile[ty + 8 * r][tx] = W[(size_t)(kb + ty + 8 * r) * DDIM + nb + tx];
    __syncthreads();
#pragma unroll
    for (int r = 0; r < 4; r++) {
        float x = tile[tx][ty + 8 * r];
        __half h = __float2half_rn(x);
        size_t o = (size_t)(nb + ty + 8 * r) * DDIM + kb + tx;
        WTh[o] = h;
        WTl[o] = __float2half_rn(x - __half2float(h));
    }
}

// XOR swizzle: 64-byte k-rows (32 halves), 4 chunks of 16B per row.
#define OPB 8192   // bytes per operand tile: 128 rows * 64 B

__device__ __forceinline__ uint32_t swz_off(int row, int chunk) {
    return (uint32_t)(row * 64 + ((chunk ^ ((row >> 1) & 3)) << 4));
}

template <int N> __device__ __forceinline__ void cpwait() {
    asm volatile("cp.async.wait_group %0;\n" ::"n"(N));
}

// =====================================================================
// Shared GEMM core. MODE_CT: 2 = fp32 store; 3 = runtime mode (0: bias +
// hi/lo split store; 1: tanh+bias, transposed fp16 store).
// SPLIT: 3 mma passes (Ah*Bh + Ah*Bl + Al*Bh), fp32 accum.
// Stage prefetch LDGSTS interleaved into the first MMA pass of each iter.
// =====================================================================
template <int MODE_CT, bool SPLIT>
__device__ __forceinline__ void gemm_core(
    const __half* __restrict__ Ah, const __half* __restrict__ Al,
    const __half* __restrict__ Bh, const __half* __restrict__ Bl,
    void* __restrict__ C0b, void* __restrict__ C1b,
    const float* __restrict__ bias,
    int K, int lda, int ldb, int ldc, int gm, int gn, int rtmode, char* smem) {
    constexpr int NSTG = SPLIT ? 3 : 6;
    constexpr int NAR  = SPLIT ? 4 : 2;
    constexpr int STGB = NAR * OPB;

    const int tid  = threadIdx.x;
    const int lane = tid & 31;
    const int warp = tid >> 5;
    const int wm = warp & 1;
    const int wn = warp >> 1;
    const int nk = K >> 5;

    float c[4][4][4];
#pragma unroll
    for (int i = 0; i < 4; i++)
#pragma unroll
        for (int j = 0; j < 4; j++)
#pragma unroll
            for (int r = 0; r < 4; r++) c[i][j][r] = 0.f;

    // full stage load (prologue only)
    auto load_stage = [&](int s, int kt) {
        if (kt < nk) {
            char* stg = smem + s * STGB;
            const int k0 = kt * 32;
#pragma unroll
            for (int op = 0; op < NAR; op++) {
                const __half* base;
                int r0, ld;
                if (SPLIT) {
                    base = (op == 0) ? Ah : (op == 1) ? Al : (op == 2) ? Bh : Bl;
                    r0 = (op < 2) ? gm : gn;
                    ld = (op < 2) ? lda : ldb;
                } else {
                    base = (op == 0) ? Ah : Bh;
                    r0 = (op == 0) ? gm : gn;
                    ld = (op == 0) ? lda : ldb;
                }
                char* dst0 = stg + op * OPB;
#pragma unroll
                for (int it = 0; it < 2; it++) {
                    int qq = tid + it * 256;
                    int r = qq >> 2, cc = qq & 3;
                    uint32_t dst = smem_u32(dst0 + swz_off(r, cc));
                    const __half* src = base + (size_t)(r0 + r) * ld + k0 + cc * 8;
                    asm volatile("cp.async.cg.shared.global [%0], [%1], 16;\n"
                                 ::"r"(dst), "l"(src));
                }
            }
        }
        asm volatile("cp.async.commit_group;\n");
    };

    // quarter-stage prefetch chunk c in [0,4) for stage s, k-tile ktn
    auto ldg_chunk = [&](int cchunk, int s, int ktn) {
        if (ktn < nk) {
            char* stg = smem + s * STGB;
            const int k0 = ktn * 32;
            if (SPLIT) {
                const __half* base = (cchunk == 0) ? Ah : (cchunk == 1) ? Al
                                   : (cchunk == 2) ? Bh : Bl;
                const int r0 = (cchunk < 2) ? gm : gn;
                const int ld = (cchunk < 2) ? lda : ldb;
                char* dst0 = stg + cchunk * OPB;
#pragma unroll
                for (int it = 0; it < 2; it++) {
                    int qq = tid + it * 256;
                    int r = qq >> 2, cc = qq & 3;
                    uint32_t dst = smem_u32(dst0 + swz_off(r, cc));
                    const __half* src = base + (size_t)(r0 + r) * ld + k0 + cc * 8;
                    asm volatile("cp.async.cg.shared.global [%0], [%1], 16;\n"
                                 ::"r"(dst), "l"(src));
                }
            } else {
                const int op = cchunk >> 1, it = cchunk & 1;
                const __half* base = (op == 0) ? Ah : Bh;
                const int r0 = (op == 0) ? gm : gn;
                const int ld = (op == 0) ? lda : ldb;
                char* dst0 = stg + op * OPB;
                int qq = tid + it * 256;
                int r = qq >> 2, cc = qq & 3;
                uint32_t dst = smem_u32(dst0 + swz_off(r, cc));
                const __half* src = base + (size_t)(r0 + r) * ld + k0 + cc * 8;
                asm volatile("cp.async.cg.shared.global [%0], [%1], 16;\n"
                             ::"r"(dst), "l"(src));
            }
        }
    };

#pragma unroll
    for (int t = 0; t < NSTG - 1; t++) load_stage(t, t);

    uint32_t ah[4][4], al[4][4], bh[4][2], bl[4][2];

    auto load_frags = [&](const char* stg, int ks) {
        const char* sa = stg;
        const char* sb = stg + (SPLIT ? 2 : 1) * OPB;
#pragma unroll
        for (int i = 0; i < 4; i++) {
            int row = wm * 64 + i * 16 + (lane & 15);
            uint32_t o = swz_off(row, ks * 2 + (lane >> 4));
            uint32_t a0 = smem_u32(sa + o);
            asm volatile("ldmatrix.sync.aligned.m8n8.x4.shared.b16 {%0,%1,%2,%3}, [%4];"
                         : "=r"(ah[i][0]), "=r"(ah[i][1]), "=r"(ah[i][2]), "=r"(ah[i][3])
                         : "r"(a0));
            if (SPLIT) {
                uint32_t a1 = smem_u32(sa + OPB + o);
                asm volatile("ldmatrix.sync.aligned.m8n8.x4.shared.b16 {%0,%1,%2,%3}, [%4];"
                             : "=r"(al[i][0]), "=r"(al[i][1]), "=r"(al[i][2]), "=r"(al[i][3])
                             : "r"(a1));
            }
        }
        // B via x4: lanes 0-7 -> (j,k0), 8-15 -> (j,k1), 16-23 -> (j+1,k0), 24-31 -> (j+1,k1)
#pragma unroll
        for (int j = 0; j < 4; j += 2) {
            int row = wn * 32 + (j + (lane >> 4)) * 8 + (lane & 7);
            uint32_t o = swz_off(row, ks * 2 + ((lane >> 3) & 1));
            uint32_t b0 = smem_u32(sb + o);
            asm volatile("ldmatrix.sync.aligned.m8n8.x4.shared.b16 {%0,%1,%2,%3}, [%4];"
                         : "=r"(bh[j][0]), "=r"(bh[j][1]), "=r"(bh[j + 1][0]), "=r"(bh[j + 1][1])
                         : "r"(b0));
            if (SPLIT) {
                uint32_t b1 = smem_u32(sb + OPB + o);
                asm volatile("ldmatrix.sync.aligned.m8n8.x4.shared.b16 {%0,%1,%2,%3}, [%4];"
                             : "=r"(bl[j][0]), "=r"(bl[j][1]), "=r"(bl[j + 1][0]), "=r"(bl[j + 1][1])
                             : "r"(b1));
            }
        }
    };

#define MMA16(AA, BB_)                                                                       \
    asm volatile("mma.sync.aligned.m16n8k16.row.col.f32.f16.f16.f32 "                        \
                 "{%0,%1,%2,%3}, {%4,%5,%6,%7}, {%8,%9}, {%0,%1,%2,%3};"                     \
                 : "+f"(c[i][j][0]), "+f"(c[i][j][1]), "+f"(c[i][j][2]), "+f"(c[i][j][3])    \
                 : "r"(AA[i][0]), "r"(AA[i][1]), "r"(AA[i][2]), "r"(AA[i][3]),               \
                   "r"(BB_[j][0]), "r"(BB_[j][1]))

    auto mmaAB = [&](uint32_t (*A)[4], uint32_t (*B)[2]) {
#pragma unroll
        for (int i = 0; i < 4; i++)
#pragma unroll
            for (int j = 0; j < 4; j++) MMA16(A, B);
    };

    for (int kt = 0; kt < nk; kt++) {
        cpwait<NSTG - 2>();
        __syncthreads();
        const char* stg = smem + (kt % NSTG) * STGB;
        const int s2 = (kt + NSTG - 1) % NSTG;
        const int ktn = kt + NSTG - 1;

        load_frags(stg, 0);
        // hh pass (ks=0) with quarter-stage prefetch interleaved per i-iter
#pragma unroll
        for (int i = 0; i < 4; i++) {
#pragma unroll
            for (int j = 0; j < 4; j++) MMA16(ah, bh);
            ldg_chunk(i, s2, ktn);
        }
        asm volatile("cp.async.commit_group;\n");
        if (SPLIT) {
            mmaAB(ah, bl);
            mmaAB(al, bh);
        }
        load_frags(stg, 1);
        mmaAB(ah, bh);
        if (SPLIT) {
            mmaAB(ah, bl);
            mmaAB(al, bh);
        }
    }

    __syncthreads();

    if (MODE_CT == 2) {
        float* C = (float*)C0b;
#pragma unroll
        for (int i = 0; i < 4; i++)
#pragma unroll
            for (int j = 0; j < 4; j++) {
                int row = gm + wm * 64 + i * 16 + (lane >> 2);
                int col = gn + wn * 32 + j * 8 + ((lane & 3) << 1);
                float2 v0; v0.x = c[i][j][0]; v0.y = c[i][j][1];
                float2 v1; v1.x = c[i][j][2]; v1.y = c[i][j][3];
                *(float2*)(C + (size_t)row * ldc + col) = v0;
                *(float2*)(C + (size_t)(row + 8) * ldc + col) = v1;
            }
    } else {
        if (rtmode == 0) {
            __half* Chi = (__half*)C0b;
            __half* Clo = (__half*)C1b;
#pragma unroll
            for (int i = 0; i < 4; i++)
#pragma unroll
                for (int j = 0; j < 4; j++) {
                    int row = gm + wm * 64 + i * 16 + (lane >> 2);
                    int col = gn + wn * 32 + j * 8 + ((lane & 3) << 1);
                    float b0 = bias[col], b1 = bias[col + 1];
#pragma unroll
                    for (int h = 0; h < 2; h++) {
                        float v0 = c[i][j][2 * h + 0] + b0;
                        float v1 = c[i][j][2 * h + 1] + b1;
                        __half h0 = __float2half_rn(v0), h1 = __float2half_rn(v1);
                        __half l0 = __float2half_rn(v0 - __half2float(h0));
                        __half l1 = __float2half_rn(v1 - __half2float(h1));
                        size_t o = (size_t)(row + 8 * h) * ldc + col;
                        *(__half2*)(Chi + o) = __halves2half2(h0, h1);
                        *(__half2*)(Clo + o) = __halves2half2(l0, l1);
                    }
                }
        } else {  // tanh + transposed fp16 store via smem staging
            __half* st = (__half*)smem;  // 128*136 halves = 34816 B
#pragma unroll
            for (int i = 0; i < 4; i++)
#pragma unroll
                for (int j = 0; j < 4; j++) {
                    int row = wm * 64 + i * 16 + (lane >> 2);
                    int col = wn * 32 + j * 8 + ((lane & 3) << 1);
                    float b0 = bias[gn + col], b1 = bias[gn + col + 1];
                    st[(col + 0) * 136 + row + 0] = __float2half_rn(tanhf(c[i][j][0] + b0));
                    st[(col + 1) * 136 + row + 0] = __float2half_rn(tanhf(c[i][j][1] + b1));
                    st[(col + 0) * 136 + row + 8] = __float2half_rn(tanhf(c[i][j][2] + b0));
                    st[(col + 1) * 136 + row + 8] = __float2half_rn(tanhf(c[i][j][3] + b1));
                }
            __syncthreads();
            __half* C = (__half*)C0b;
            for (int qq = tid; qq < 128 * 128 / 8; qq += 256) {
                int n = qq >> 4, m = (qq & 15) << 3;
                *(uint4*)(C + (size_t)(gn + n) * ldc + gm + m) = *(const uint4*)(st + n * 136 + m);
            }
        }
    }
#undef MMA16
}

// --------- projection kernel: z picks {Q, K} ---------
struct ProjSet {
    const __half *Ah, *Al, *Bh, *Bl;
    __half *C0, *C1;
    const float* bias;
};

__global__ void __launch_bounds__(256, 2)
gemm_proj(ProjSet p0, ProjSet p1) {
    extern __shared__ __align__(128) char smem[];
    const ProjSet& p = (blockIdx.z == 0) ? p0 : p1;
    gemm_core<3, true>(p.Ah, p.Al, p.Bh, p.Bl, p.C0, p.C1, p.bias,
                       DDIM, DDIM, DDIM, DDIM,
                       blockIdx.y * 128, blockIdx.x * 128, 0, smem);
}

// --------- merged V-projection + scores launch ---------
// z in [0,4): V-projection tiles (tanh + transposed store), z-first for backfill
// z in [4,12): scores batch z-4
__global__ void __launch_bounds__(256, 2)
gemm_sv(const __half* Qph, const __half* Qpl, const __half* Kph, const __half* Kpl,
        float* S,
        const __half* vh, const __half* vl, const __half* Wvh, const __half* Wvl,
        __half* VpT, const float* bv) {
    extern __shared__ __align__(128) char smem[];
    int z = blockIdx.z;
    if (z >= 4) {
        int b = z - 4;
        gemm_core<2, true>(Qph + (size_t)b * SQL * DDIM, Qpl + (size_t)b * SQL * DDIM,
                           Kph + (size_t)b * SKL * DDIM, Kpl + (size_t)b * SKL * DDIM,
                           S + (size_t)b * SQL * SKL, nullptr, nullptr,
                           DDIM, DDIM, DDIM, SKL,
                           blockIdx.y * 128, blockIdx.x * 128, 2, smem);
    } else {
        // 4 z-slices x 256 xy-blocks = 1024 tiles of the 16384x1024 V projection
        int t = z * 256 + blockIdx.y * 16 + blockIdx.x;   // 0..1023
        gemm_core<3, true>(vh, vl, Wvh, Wvl, VpT, nullptr, bv,
                           DDIM, DDIM, DDIM, BB * SKL,
                           (t >> 3) * 128, (t & 7) * 128, 1, smem);
    }
}

// --------- PV kernel (single-pass fp16) ---------
__global__ void __launch_bounds__(256, 2)
gemm_pv(const __half* __restrict__ P, const __half* __restrict__ VpT,
        float* __restrict__ O) {
    extern __shared__ __align__(128) char smem[];
    int b = blockIdx.z;
    gemm_core<2, false>(P + (size_t)b * SQL * SKL, nullptr,
                        VpT + (size_t)b * SKL, nullptr,
                        O + (size_t)b * SQL * DDIM, nullptr, nullptr,
                        SKL, SKL, BB * SKL, DDIM,
                        blockIdx.y * 128, blockIdx.x * 128, 2, smem);
}

// ---------------- vectorized softmax (+ int32 bool-mask add) -> fp16 P ----------------
__global__ void softmax_k(const float* __restrict__ S, const int* __restrict__ mask,
                          __half* __restrict__ P) {
    int row = blockIdx.x;
    int b = row >> 11;
    int t = threadIdx.x;
    const float4* s4 = (const float4*)(S + (size_t)row * SKL);
    const int4*   m4 = (const int4*)(mask + (size_t)b * SKL);

    float4 v[2];
    float mx = -3.4e38f;
#pragma unroll
    for (int i = 0; i < 2; i++) {
        float4 sv = s4[t + i * 256];
        int4 mv = m4[t + i * 256];
        sv.x += mv.x ? 1.0f : 0.0f;
        sv.y += mv.y ? 1.0f : 0.0f;
        sv.z += mv.z ? 1.0f : 0.0f;
        sv.w += mv.w ? 1.0f : 0.0f;
        v[i] = sv;
        mx = fmaxf(mx, fmaxf(fmaxf(sv.x, sv.y), fmaxf(sv.z, sv.w)));
    }
    __shared__ float red[8];
#pragma unroll
    for (int o = 16; o > 0; o >>= 1) mx = fmaxf(mx, __shfl_xor_sync(0xffffffffu, mx, o));
    if ((t & 31) == 0) red[t >> 5] = mx;
    __syncthreads();
    mx = red[0];
#pragma unroll
    for (int i = 1; i < 8; i++) mx = fmaxf(mx, red[i]);
    __syncthreads();

    float sum = 0.f;
#pragma unroll
    for (int i = 0; i < 2; i++) {
        v[i].x = __expf(v[i].x - mx);
        v[i].y = __expf(v[i].y - mx);
        v[i].z = __expf(v[i].z - mx);
        v[i].w = __expf(v[i].w - mx);
        sum += v[i].x + v[i].y + v[i].z + v[i].w;
    }
#pragma unroll
    for (int o = 16; o > 0; o >>= 1) sum += __shfl_xor_sync(0xffffffffu, sum, o);
    if ((t & 31) == 0) red[t >> 5] = sum;
    __syncthreads();
    sum = red[0];
#pragma unroll
    for (int i = 1; i < 8; i++) sum += red[i];

    float inv = 1.0f / sum;
    __half* Pr = P + (size_t)row * SKL;
#pragma unroll
    for (int i = 0; i < 2; i++) {
        __half2 h0 = __floats2half2_rn(v[i].x * inv, v[i].y * inv);
        __half2 h1 = __floats2half2_rn(v[i].z * inv, v[i].w * inv);
        uint2 pk;
        pk.x = *(uint32_t*)&h0;
        pk.y = *(uint32_t*)&h1;
        *(uint2*)(Pr + 4 * (t + i * 256)) = pk;
    }
}

// ---------------- launch ----------------
extern "C" void kernel_launch(void* const* d_in, const int* in_sizes, int n_in,
                              void* d_out, int out_size) {
    const float* q  = (const float*)d_in[0];
    const float* k  = (const float*)d_in[1];
    const float* v  = (const float*)d_in[2];
    const int*   mask = (const int*)d_in[3];
    const float* Wq = (const float*)d_in[4];
    const float* bq = (const float*)d_in[5];
    const float* Wk = (const float*)d_in[6];
    const float* bk = (const float*)d_in[7];
    const float* Wv = (const float*)d_in[8];
    const float* bv = (const float*)d_in[9];

    __half *qh, *ql, *kh, *kl, *vh, *vl;
    __half *Wqh, *Wql, *Wkh, *Wkl, *Wvh, *Wvl;
    __half *Qph, *Qpl, *Kph, *Kpl, *VpT, *P;
    float* S;
    cudaGetSymbolAddress((void**)&qh,  g_qh);  cudaGetSymbolAddress((void**)&ql,  g_ql);
    cudaGetSymbolAddress((void**)&kh,  g_kh);  cudaGetSymbolAddress((void**)&kl,  g_kl);
    cudaGetSymbolAddress((void**)&vh,  g_vh);  cudaGetSymbolAddress((void**)&vl,  g_vl);
    cudaGetSymbolAddress((void**)&Wqh, g_Wqh); cudaGetSymbolAddress((void**)&Wql, g_Wql);
    cudaGetSymbolAddress((void**)&Wkh, g_Wkh); cudaGetSymbolAddress((void**)&Wkl, g_Wkl);
    cudaGetSymbolAddress((void**)&Wvh, g_Wvh); cudaGetSymbolAddress((void**)&Wvl, g_Wvl);
    cudaGetSymbolAddress((void**)&Qph, g_Qph); cudaGetSymbolAddress((void**)&Qpl, g_Qpl);
    cudaGetSymbolAddress((void**)&Kph, g_Kph); cudaGetSymbolAddress((void**)&Kpl, g_Kpl);
    cudaGetSymbolAddress((void**)&VpT, g_VpT);
    cudaGetSymbolAddress((void**)&S,   g_S);
    cudaGetSymbolAddress((void**)&P,   g_P);

    const int SM_SPLIT  = 3 * 4 * OPB;  // 98304
    const int SM_SINGLE = 6 * 2 * OPB;  // 98304
    cudaFuncSetAttribute(gemm_proj, cudaFuncAttributeMaxDynamicSharedMemorySize, SM_SPLIT);
    cudaFuncSetAttribute(gemm_sv,   cudaFuncAttributeMaxDynamicSharedMemorySize, SM_SPLIT);
    cudaFuncSetAttribute(gemm_pv,   cudaFuncAttributeMaxDynamicSharedMemorySize, SM_SINGLE);

    int n4 = BB * SQL * DDIM / 4;
    cvt_split3<<<dim3(n4 / 256, 3), 256>>>(q, qh, ql, k, kh, kl, v, vh, vl);

    wtrans3<<<dim3(32, 32, 3), dim3(32, 8)>>>(Wq, Wqh, Wql, Wk, Wkh, Wkl, Wv, Wvh, Wvl);

    // Q & K projections: M=16384, N=1024, K=1024 (3-pass split)
    ProjSet pq{qh, ql, Wqh, Wql, Qph, Qpl, bq};
    ProjSet pk{kh, kl, Wkh, Wkl, Kph, Kpl, bk};
    gemm_proj<<<dim3(8, 128, 2), 256, SM_SPLIT>>>(pq, pk);

    // V projection (z 0-3) + scores for 8 batches (z 4-11), one launch
    gemm_sv<<<dim3(16, 16, 12), 256, SM_SPLIT>>>(
        Qph, Qpl, Kph, Kpl, S, vh, vl, Wvh, Wvl, VpT, bv);

    // Softmax (+int mask) -> P fp16
    softmax_k<<<BB * SQL, 256>>>(S, mask, P);

    // Output: per batch, O = P · VpT^T (M=2048, N=1024, K=2048), single-pass fp16
    gemm_pv<<<dim3(8, 16, BB), 256, SM_SINGLE>>>(P, VpT, (float*)d_out);
}